// round 1
// baseline (speedup 1.0000x reference)
#include <cuda_runtime.h>
#include <math.h>

// Problem constants (B=32, N=256, D=2048, d=512, M=512)
#define ROWS  8192      // B*N
#define DIN   2048      // D
#define DOUT  512       // d
#define KC    6144      // 3*D (im2col K)
#define NKEYS 1024      // 2*M
#define NSEQ  256       // N

// -------- scratch (device globals; no allocation allowed) --------
__device__ float g_Wt[KC * DOUT];   // transposed conv weight: Wt[kk][o], kk = seg*2048 + c
__device__ float g_kv[NKEYS];       // keys_j . cls_mem_w[512:1024]
__device__ float g_kkn[NKEYS];      // ||keys_j||^2
__device__ float g_w1dot[ROWS];     // q . cls_mem_w[0:512]
__device__ float g_qq[ROWS];        // ||q||^2

// ============================================================
// 1) Transpose conv_w (d, D, 3) -> Wt[(seg*2048+c)][o]
// ============================================================
__global__ void transpose_w_kernel(const float* __restrict__ conv_w)
{
    __shared__ float tile[32][33];
    const int tile_o = blockIdx.x * 32;   // over DOUT (16 tiles)
    const int tile_k = blockIdx.y * 32;   // over KC (192 tiles)
    const int tx = threadIdx.x;           // 0..31
    const int ty = threadIdx.y;           // 0..7
#pragma unroll
    for (int rr = 0; rr < 4; rr++) {
        int o  = tile_o + ty + rr * 8;
        int kk = tile_k + tx;
        int c   = kk & 2047;
        int seg = kk >> 11;
        tile[ty + rr * 8][tx] = conv_w[(size_t)o * KC + c * 3 + seg];
    }
    __syncthreads();
#pragma unroll
    for (int rr = 0; rr < 4; rr++) {
        int kk = tile_k + ty + rr * 8;
        int o  = tile_o + tx;
        g_Wt[(size_t)kk * DOUT + o] = tile[tx][ty + rr * 8];
    }
}

// ============================================================
// 2) Conv-as-GEMM: E[row][o] = relu( sum_kk A[row][kk] * Wt[kk][o] + b[o] )
//    A[row][seg*2048+c] = X[row + seg - 1][c] (zero outside batch-row range)
//    Tile 128x128x16, 256 threads, 8x8 per thread.
// ============================================================
__global__ void __launch_bounds__(256, 2) conv_gemm_kernel(
    const float* __restrict__ X,
    const float* __restrict__ bias,
    float* __restrict__ E)
{
    __shared__ float As[16][132];
    __shared__ float Bs[16][128];
    const int tid = threadIdx.x;
    const int bm = blockIdx.y * 128;
    const int bn = blockIdx.x * 128;
    const int tx = tid & 15;
    const int ty = tid >> 4;
    const int la_m  = tid >> 2;          // 0..63
    const int la_k4 = (tid & 3) * 4;     // 0,4,8,12
    const int lb_k  = tid >> 5;          // 0..7
    const int lb_o  = (tid & 31) * 4;    // 0..124

    float acc[8][8];
#pragma unroll
    for (int i = 0; i < 8; i++)
#pragma unroll
        for (int j = 0; j < 8; j++) acc[i][j] = 0.f;

    for (int k0 = 0; k0 < KC; k0 += 16) {
        const int seg = k0 >> 11;                 // whole 16-chunk lies in one segment
        const int c   = (k0 & 2047) + la_k4;
        const int sh  = seg - 1;
        // ---- A tile (128 x 16), stored transposed As[k][m] ----
#pragma unroll
        for (int p = 0; p < 2; p++) {
            const int m  = la_m + p * 64;
            const int gm = bm + m;
            const int n  = gm & (NSEQ - 1);
            const int sn = n + sh;
            float4 v = make_float4(0.f, 0.f, 0.f, 0.f);
            if (sn >= 0 && sn < NSEQ)
                v = *reinterpret_cast<const float4*>(X + (size_t)(gm + sh) * DIN + c);
            As[la_k4 + 0][m] = v.x;
            As[la_k4 + 1][m] = v.y;
            As[la_k4 + 2][m] = v.z;
            As[la_k4 + 3][m] = v.w;
        }
        // ---- B tile (16 x 128) ----
#pragma unroll
        for (int p = 0; p < 2; p++) {
            const int kk = k0 + lb_k + p * 8;
            float4 v = *reinterpret_cast<const float4*>(g_Wt + (size_t)kk * DOUT + bn + lb_o);
            *reinterpret_cast<float4*>(&Bs[lb_k + p * 8][lb_o]) = v;
        }
        __syncthreads();
#pragma unroll
        for (int kk = 0; kk < 16; kk++) {
            float4 a0 = *reinterpret_cast<const float4*>(&As[kk][ty * 8]);
            float4 a1 = *reinterpret_cast<const float4*>(&As[kk][ty * 8 + 4]);
            float4 b0 = *reinterpret_cast<const float4*>(&Bs[kk][tx * 8]);
            float4 b1 = *reinterpret_cast<const float4*>(&Bs[kk][tx * 8 + 4]);
            float a[8] = {a0.x, a0.y, a0.z, a0.w, a1.x, a1.y, a1.z, a1.w};
            float b[8] = {b0.x, b0.y, b0.z, b0.w, b1.x, b1.y, b1.z, b1.w};
#pragma unroll
            for (int i = 0; i < 8; i++)
#pragma unroll
                for (int j = 0; j < 8; j++)
                    acc[i][j] = fmaf(a[i], b[j], acc[i][j]);
        }
        __syncthreads();
    }
    // epilogue: bias + relu
#pragma unroll
    for (int i = 0; i < 8; i++) {
        const int row = bm + ty * 8 + i;
#pragma unroll
        for (int j = 0; j < 8; j += 4) {
            const int col = bn + tx * 8 + j;
            float4 v;
            v.x = fmaxf(acc[i][j + 0] + __ldg(&bias[col + 0]), 0.f);
            v.y = fmaxf(acc[i][j + 1] + __ldg(&bias[col + 1]), 0.f);
            v.z = fmaxf(acc[i][j + 2] + __ldg(&bias[col + 2]), 0.f);
            v.w = fmaxf(acc[i][j + 3] + __ldg(&bias[col + 3]), 0.f);
            *reinterpret_cast<float4*>(E + (size_t)row * DOUT + col) = v;
        }
    }
}

// ============================================================
// 3) Per-key prep: kv[j] = keys_j . w2, kkn[j] = ||keys_j||^2
// ============================================================
__global__ void prep_keys_kernel(const float* __restrict__ nor_keys,
                                 const float* __restrict__ abn_keys,
                                 const float* __restrict__ cls_mem_w)
{
    const int j = blockIdx.x * 8 + (threadIdx.x >> 5);
    const int lane = threadIdx.x & 31;
    const float* key = (j < 512) ? (nor_keys + (size_t)j * DOUT)
                                 : (abn_keys + (size_t)(j - 512) * DOUT);
    const float* w2 = cls_mem_w + DOUT;
    float kv = 0.f, kn = 0.f;
#pragma unroll
    for (int t = 0; t < 4; t++) {
        const int c = (lane + t * 32) * 4;
        float4 k4 = *reinterpret_cast<const float4*>(key + c);
        float4 w4 = *reinterpret_cast<const float4*>(w2 + c);
        kv += k4.x * w4.x + k4.y * w4.y + k4.z * w4.z + k4.w * w4.w;
        kn += k4.x * k4.x + k4.y * k4.y + k4.z * k4.z + k4.w * k4.w;
    }
#pragma unroll
    for (int o = 16; o; o >>= 1) {
        kv += __shfl_xor_sync(0xffffffffu, kv, o);
        kn += __shfl_xor_sync(0xffffffffu, kn, o);
    }
    if (lane == 0) { g_kv[j] = kv; g_kkn[j] = kn; }
}

// ============================================================
// 4) Per-row stats: p_score = sigmoid(q.cls_w + cls_b),
//    w1dot = q.w1, qq = ||q||^2
// ============================================================
__global__ void rowstats_kernel(const float* __restrict__ E,
                                const float* __restrict__ cls_w,
                                const float* __restrict__ cls_b,
                                const float* __restrict__ cls_mem_w,
                                float* __restrict__ p_out)
{
    const int row  = blockIdx.x * 8 + (threadIdx.x >> 5);
    const int lane = threadIdx.x & 31;
    const float* q = E + (size_t)row * DOUT;
    float d0 = 0.f, d1 = 0.f, qq = 0.f;
#pragma unroll
    for (int t = 0; t < 4; t++) {
        const int c = (lane + t * 32) * 4;
        float4 v  = *reinterpret_cast<const float4*>(q + c);
        float4 w0 = *reinterpret_cast<const float4*>(cls_w + c);
        float4 w1 = *reinterpret_cast<const float4*>(cls_mem_w + c);
        d0 += v.x * w0.x + v.y * w0.y + v.z * w0.z + v.w * w0.w;
        d1 += v.x * w1.x + v.y * w1.y + v.z * w1.z + v.w * w1.w;
        qq += v.x * v.x + v.y * v.y + v.z * v.z + v.w * v.w;
    }
#pragma unroll
    for (int o = 16; o; o >>= 1) {
        d0 += __shfl_xor_sync(0xffffffffu, d0, o);
        d1 += __shfl_xor_sync(0xffffffffu, d1, o);
        qq += __shfl_xor_sync(0xffffffffu, qq, o);
    }
    if (lane == 0) {
        p_out[row]    = 1.f / (1.f + __expf(-(d0 + cls_b[0])));
        g_w1dot[row]  = d1;
        g_qq[row]     = qq;
    }
}

// ============================================================
// 5) Fused read: per row over 1024 keys — online softmax (max,sum,dot-kv),
//    per-half argmax -> updated_p_score + both compactness losses.
//    GEMM tiling: 64 rows x 128 keys x 16 K per block, loop 8 key-tiles.
// ============================================================
__global__ void __launch_bounds__(256) read_kernel(
    const float* __restrict__ E,
    const float* __restrict__ nor_keys,
    const float* __restrict__ abn_keys,
    const float* __restrict__ cls_mem_b,
    float* __restrict__ up_out,
    float* __restrict__ nor_out,
    float* __restrict__ abn_out)
{
    __shared__ float As[16][68];
    __shared__ float Ks[16][132];
    const int tid = threadIdx.x;
    const int bm  = blockIdx.x * 64;
    const int tx  = tid & 15;
    const int ty  = tid >> 4;
    const int la_m  = tid >> 2;        // 0..63
    const int la_k4 = (tid & 3) * 4;

    float m_r[4], l_r[4], d_r[4];
    float bv[2][4];
    int   bi[2][4];
#pragma unroll
    for (int i = 0; i < 4; i++) {
        m_r[i] = -INFINITY; l_r[i] = 0.f; d_r[i] = 0.f;
        bv[0][i] = -INFINITY; bv[1][i] = -INFINITY;
        bi[0][i] = 0; bi[1][i] = 0;
    }

    for (int nk = 0; nk < 8; nk++) {
        const float* keys = (nk < 4) ? (nor_keys + (size_t)nk * 128 * DOUT)
                                     : (abn_keys + (size_t)(nk - 4) * 128 * DOUT);
        float s[4][8];
#pragma unroll
        for (int i = 0; i < 4; i++)
#pragma unroll
            for (int j = 0; j < 8; j++) s[i][j] = 0.f;

        for (int k0 = 0; k0 < DOUT; k0 += 16) {
            // A tile 64x16 (one pass)
            {
                float4 v = *reinterpret_cast<const float4*>(
                    E + (size_t)(bm + la_m) * DOUT + k0 + la_k4);
                As[la_k4 + 0][la_m] = v.x;
                As[la_k4 + 1][la_m] = v.y;
                As[la_k4 + 2][la_m] = v.z;
                As[la_k4 + 3][la_m] = v.w;
            }
            // K tile 128x16 (two passes)
#pragma unroll
            for (int p = 0; p < 2; p++) {
                const int jj = la_m + p * 64;
                float4 v = *reinterpret_cast<const float4*>(
                    keys + (size_t)jj * DOUT + k0 + la_k4);
                Ks[la_k4 + 0][jj] = v.x;
                Ks[la_k4 + 1][jj] = v.y;
                Ks[la_k4 + 2][jj] = v.z;
                Ks[la_k4 + 3][jj] = v.w;
            }
            __syncthreads();
#pragma unroll
            for (int kk = 0; kk < 16; kk++) {
                float4 av = *reinterpret_cast<const float4*>(&As[kk][ty * 4]);
                float4 b0 = *reinterpret_cast<const float4*>(&Ks[kk][tx * 8]);
                float4 b1 = *reinterpret_cast<const float4*>(&Ks[kk][tx * 8 + 4]);
                float a[4] = {av.x, av.y, av.z, av.w};
                float b[8] = {b0.x, b0.y, b0.z, b0.w, b1.x, b1.y, b1.z, b1.w};
#pragma unroll
                for (int i = 0; i < 4; i++)
#pragma unroll
                    for (int j = 0; j < 8; j++)
                        s[i][j] = fmaf(a[i], b[j], s[i][j]);
            }
            __syncthreads();
        }
        // fold tile into online reductions
        const int h = nk >> 2;
        float kvj[8];
#pragma unroll
        for (int j = 0; j < 8; j++) kvj[j] = g_kv[nk * 128 + tx * 8 + j];
#pragma unroll
        for (int i = 0; i < 4; i++) {
            float tm = s[i][0];
#pragma unroll
            for (int j = 1; j < 8; j++) tm = fmaxf(tm, s[i][j]);
            const float mnew  = fmaxf(m_r[i], tm);
            const float scale = __expf(m_r[i] - mnew);
            l_r[i] *= scale; d_r[i] *= scale; m_r[i] = mnew;
#pragma unroll
            for (int j = 0; j < 8; j++) {
                const float e = __expf(s[i][j] - mnew);
                l_r[i] += e;
                d_r[i] += e * kvj[j];
                if (s[i][j] > bv[h][i]) { bv[h][i] = s[i][j]; bi[h][i] = nk * 128 + tx * 8 + j; }
            }
        }
    }
    // reduce across tx (16 lanes of a half-warp)
#pragma unroll
    for (int off = 1; off < 16; off <<= 1) {
#pragma unroll
        for (int i = 0; i < 4; i++) {
            const float mo = __shfl_xor_sync(0xffffffffu, m_r[i], off);
            const float lo = __shfl_xor_sync(0xffffffffu, l_r[i], off);
            const float dd = __shfl_xor_sync(0xffffffffu, d_r[i], off);
            const float M  = fmaxf(m_r[i], mo);
            const float s1 = __expf(m_r[i] - M);
            const float s2 = __expf(mo - M);
            l_r[i] = l_r[i] * s1 + lo * s2;
            d_r[i] = d_r[i] * s1 + dd * s2;
            m_r[i] = M;
#pragma unroll
            for (int hh = 0; hh < 2; hh++) {
                const float bvo = __shfl_xor_sync(0xffffffffu, bv[hh][i], off);
                const int   bio = __shfl_xor_sync(0xffffffffu, bi[hh][i], off);
                if (bvo > bv[hh][i]) { bv[hh][i] = bvo; bi[hh][i] = bio; }
            }
        }
    }
    if (tx == 0) {
        const float cb = cls_mem_b[0];
#pragma unroll
        for (int i = 0; i < 4; i++) {
            const int row = bm + ty * 4 + i;
            const float x = g_w1dot[row] + d_r[i] / l_r[i] + cb;
            up_out[row] = 1.f / (1.f + __expf(-x));
            const float qq = g_qq[row];
            nor_out[row] = (qq - 2.f * bv[0][i] + g_kkn[bi[0][i]]) * (1.f / 512.f);
            abn_out[row] = (qq - 2.f * bv[1][i] + g_kkn[bi[1][i]]) * (1.f / 512.f);
        }
    }
}

// ============================================================
// launch
// ============================================================
extern "C" void kernel_launch(void* const* d_in, const int* in_sizes, int n_in,
                              void* d_out, int out_size)
{
    const float* ref_nor   = (const float*)d_in[0];
    // d_in[1] = ref_abn : dead code (only feeds the discarded p_score[B:])
    const float* nor_keys  = (const float*)d_in[2];
    const float* abn_keys  = (const float*)d_in[3];
    const float* conv_w    = (const float*)d_in[4];
    const float* conv_b    = (const float*)d_in[5];
    const float* cls_w     = (const float*)d_in[6];
    const float* cls_b     = (const float*)d_in[7];
    const float* cls_mem_w = (const float*)d_in[8];
    const float* cls_mem_b = (const float*)d_in[9];
    // d_in[10] = epoch (unused by reference math)

    float* out      = (float*)d_out;
    float* p_score  = out;                 // (B,N)   = 8192
    float* up_score = out + ROWS;          // (B,N)   = 8192
    float* nor_loss = out + 2 * ROWS;      // (B*N,)  = 8192
    float* abn_loss = out + 3 * ROWS;      // (B*N,)  = 8192
    float* E        = out + 4 * ROWS;      // (B,N,d) = 4194304

    transpose_w_kernel<<<dim3(16, 192), dim3(32, 8)>>>(conv_w);
    conv_gemm_kernel<<<dim3(4, 64), 256>>>(ref_nor, conv_b, E);
    prep_keys_kernel<<<128, 256>>>(nor_keys, abn_keys, cls_mem_w);
    rowstats_kernel<<<1024, 256>>>(E, cls_w, cls_b, cls_mem_w, p_score);
    read_kernel<<<128, 256>>>(E, nor_keys, abn_keys, cls_mem_b,
                              up_score, nor_loss, abn_loss);
}

// round 3
// speedup vs baseline: 2.1173x; 2.1173x over previous
#include <cuda_runtime.h>
#include <cuda_bf16.h>
#include <math.h>
#include <stdint.h>

// Problem constants (B=32, N=256, D=2048, d=512, M=512)
#define ROWS  8192      // B*N
#define DIN   2048      // D
#define DOUT  512       // d
#define KC    6144      // 3*D (im2col K)
#define NKEYS 1024      // 2*M
#define NSEQ  256       // N

// ---------------- scratch (device globals; no allocation allowed) ----------------
__device__ __nv_bfloat16 g_Xhi[ROWS * DIN];
__device__ __nv_bfloat16 g_Xlo[ROWS * DIN];
__device__ __nv_bfloat16 g_Whi[DOUT * KC];     // W rearranged: [o][seg*2048+c]
__device__ __nv_bfloat16 g_Wlo[DOUT * KC];
__device__ __nv_bfloat16 g_Ehi[ROWS * DOUT];
__device__ __nv_bfloat16 g_Elo[ROWS * DOUT];
__device__ __nv_bfloat16 g_Khi[NKEYS * DOUT];
__device__ __nv_bfloat16 g_Klo[NKEYS * DOUT];
__device__ float g_S[(size_t)ROWS * NKEYS];    // score matrix
__device__ float g_kv[NKEYS];
__device__ float g_kkn[NKEYS];
__device__ float g_w1dot[ROWS];
__device__ float g_qq[ROWS];

// ---------------- helpers ----------------
__device__ __forceinline__ uint32_t smem_u32(const void* p) {
    uint32_t a;
    asm("{ .reg .u64 t; cvta.to.shared.u64 t, %1; cvt.u32.u64 %0, t; }" : "=r"(a) : "l"(p));
    return a;
}

#define CP_ASYNC16(dst, src, sz) \
    asm volatile("cp.async.cg.shared.global [%0], [%1], 16, %2;" \
                 :: "r"(dst), "l"(src), "r"(sz))
#define CP_COMMIT() asm volatile("cp.async.commit_group;" ::: "memory")
#define CP_WAIT0()  asm volatile("cp.async.wait_group 0;" ::: "memory")
#define CP_WAIT1()  asm volatile("cp.async.wait_group 1;" ::: "memory")

#define LDMATRIX_X4(r0, r1, r2, r3, addr) \
    asm volatile("ldmatrix.sync.aligned.m8n8.x4.shared.b16 {%0,%1,%2,%3}, [%4];" \
                 : "=r"(r0), "=r"(r1), "=r"(r2), "=r"(r3) : "r"(addr))

#define MMA_BF16(d, a, b0v, b1v) \
    asm volatile("mma.sync.aligned.m16n8k16.row.col.f32.bf16.bf16.f32 " \
                 "{%0,%1,%2,%3}, {%4,%5,%6,%7}, {%8,%9}, {%0,%1,%2,%3};" \
                 : "+f"((d)[0]), "+f"((d)[1]), "+f"((d)[2]), "+f"((d)[3]) \
                 : "r"((a)[0]), "r"((a)[1]), "r"((a)[2]), "r"((a)[3]), \
                   "r"(b0v), "r"(b1v))

__device__ __forceinline__ void split_bf16(float x, uint32_t& h, uint32_t& l) {
    __nv_bfloat16 hb = __float2bfloat16(x);
    float hf = __bfloat162float(hb);
    __nv_bfloat16 lb = __float2bfloat16(x - hf);
    h = (uint32_t)__bfloat16_as_ushort(hb);
    l = (uint32_t)__bfloat16_as_ushort(lb);
}

// SMEM tile geometry: 128 rows x 32 bf16 per matrix, row pitch 80B (conflict-free ldmatrix)
#define PITCH      80
#define MAT_BYTES  (128 * PITCH)      // 10240
#define OFF_AH     0
#define OFF_AL     (1 * MAT_BYTES)
#define OFF_BH     (2 * MAT_BYTES)
#define OFF_BL     (3 * MAT_BYTES)
#define STAGE      (4 * MAT_BYTES)    // 40960
#define SMEM_BYTES (2 * STAGE)        // 81920

// ============================================================
// prep: X -> bf16 hi/lo
// ============================================================
__global__ void convert_x_kernel(const float* __restrict__ X) {
    size_t base = ((size_t)blockIdx.x * 256 + threadIdx.x) * 8;
    float4 v0 = *reinterpret_cast<const float4*>(X + base);
    float4 v1 = *reinterpret_cast<const float4*>(X + base + 4);
    float f[8] = {v0.x, v0.y, v0.z, v0.w, v1.x, v1.y, v1.z, v1.w};
    uint32_t hw[4], lw[4];
#pragma unroll
    for (int c = 0; c < 4; c++) {
        uint32_t h0, l0, h1, l1;
        split_bf16(f[2 * c], h0, l0);
        split_bf16(f[2 * c + 1], h1, l1);
        hw[c] = h0 | (h1 << 16);
        lw[c] = l0 | (l1 << 16);
    }
    *reinterpret_cast<uint4*>(g_Xhi + base) = make_uint4(hw[0], hw[1], hw[2], hw[3]);
    *reinterpret_cast<uint4*>(g_Xlo + base) = make_uint4(lw[0], lw[1], lw[2], lw[3]);
}

// ============================================================
// prep: conv_w (d, D, 3) -> W[o][seg*2048+c] bf16 hi/lo
// ============================================================
__global__ void convert_w_kernel(const float* __restrict__ conv_w) {
    int idx = blockIdx.x * 256 + threadIdx.x;     // 0 .. 512*6144-1
    int o = idx / KC;
    int kk = idx - o * KC;
    int seg = kk >> 11;
    int c = kk & 2047;
    float v = conv_w[(size_t)o * KC + c * 3 + seg];
    uint32_t h, l;
    split_bf16(v, h, l);
    g_Whi[idx] = __ushort_as_bfloat16((unsigned short)h);
    g_Wlo[idx] = __ushort_as_bfloat16((unsigned short)l);
}

// ============================================================
// prep: keys -> bf16 hi/lo (concat nor|abn)
// ============================================================
__global__ void convert_keys_kernel(const float* __restrict__ nor_keys,
                                    const float* __restrict__ abn_keys) {
    size_t e = ((size_t)blockIdx.x * 256 + threadIdx.x) * 4;
    int j = (int)(e >> 9);
    int col = (int)(e & 511);
    const float* src = (j < 512) ? (nor_keys + (size_t)j * DOUT + col)
                                 : (abn_keys + (size_t)(j - 512) * DOUT + col);
    float4 v = *reinterpret_cast<const float4*>(src);
    uint32_t h0, l0, h1, l1, h2, l2, h3, l3;
    split_bf16(v.x, h0, l0); split_bf16(v.y, h1, l1);
    split_bf16(v.z, h2, l2); split_bf16(v.w, h3, l3);
    *reinterpret_cast<uint2*>(g_Khi + e) = make_uint2(h0 | (h1 << 16), h2 | (h3 << 16));
    *reinterpret_cast<uint2*>(g_Klo + e) = make_uint2(l0 | (l1 << 16), l2 | (l3 << 16));
}

// ============================================================
// prep: kv[j] = keys_j . w2, kkn[j] = ||keys_j||^2
// ============================================================
__global__ void prep_keys_kernel(const float* __restrict__ nor_keys,
                                 const float* __restrict__ abn_keys,
                                 const float* __restrict__ cls_mem_w) {
    const int j = blockIdx.x * 8 + (threadIdx.x >> 5);
    const int lane = threadIdx.x & 31;
    const float* key = (j < 512) ? (nor_keys + (size_t)j * DOUT)
                                 : (abn_keys + (size_t)(j - 512) * DOUT);
    const float* w2 = cls_mem_w + DOUT;
    float kv = 0.f, kn = 0.f;
#pragma unroll
    for (int t = 0; t < 4; t++) {
        const int c = (lane + t * 32) * 4;
        float4 k4 = *reinterpret_cast<const float4*>(key + c);
        float4 w4 = *reinterpret_cast<const float4*>(w2 + c);
        kv += k4.x * w4.x + k4.y * w4.y + k4.z * w4.z + k4.w * w4.w;
        kn += k4.x * k4.x + k4.y * k4.y + k4.z * k4.z + k4.w * k4.w;
    }
#pragma unroll
    for (int o = 16; o; o >>= 1) {
        kv += __shfl_xor_sync(0xffffffffu, kv, o);
        kn += __shfl_xor_sync(0xffffffffu, kn, o);
    }
    if (lane == 0) { g_kv[j] = kv; g_kkn[j] = kn; }
}

// ============================================================
// shared MMA tile compute: 8 warps as 4(M)x2(N), warp tile 32x64.
// Performs the 3-pass bf16 mma over one 128x128x32 chunk resident in SMEM.
// ============================================================
__device__ __forceinline__ void mma_chunk(uint32_t sb, float acc[2][8][4],
                                          int wm, int wn, int lane)
{
    const int lrow  = lane & 15;
    const int khalf = lane >> 4;
#pragma unroll
    for (int ks = 0; ks < 2; ks++) {
        const uint32_t kbyte = ks * 32 + khalf * 16;
        uint32_t ah[2][4], al[2][4];
#pragma unroll
        for (int mf = 0; mf < 2; mf++) {
            const uint32_t ra = sb + OFF_AH + (wm + mf * 16 + lrow) * PITCH + kbyte;
            LDMATRIX_X4(ah[mf][0], ah[mf][1], ah[mf][2], ah[mf][3], ra);
            const uint32_t rl = sb + OFF_AL + (wm + mf * 16 + lrow) * PITCH + kbyte;
            LDMATRIX_X4(al[mf][0], al[mf][1], al[mf][2], al[mf][3], rl);
        }
        uint32_t bh[4][4], bl[4][4];
#pragma unroll
        for (int nq = 0; nq < 4; nq++) {
            const uint32_t rb = sb + OFF_BH + (wn + nq * 16 + lrow) * PITCH + kbyte;
            LDMATRIX_X4(bh[nq][0], bh[nq][1], bh[nq][2], bh[nq][3], rb);
            const uint32_t rl = sb + OFF_BL + (wn + nq * 16 + lrow) * PITCH + kbyte;
            LDMATRIX_X4(bl[nq][0], bl[nq][1], bl[nq][2], bl[nq][3], rl);
        }
#pragma unroll
        for (int mf = 0; mf < 2; mf++)
#pragma unroll
            for (int nq = 0; nq < 4; nq++)
#pragma unroll
                for (int nh = 0; nh < 2; nh++) {
                    float* d = acc[mf][nq * 2 + nh];
                    MMA_BF16(d, ah[mf], bh[nq][nh], bh[nq][nh + 2]);   // AhBh
                    MMA_BF16(d, ah[mf], bl[nq][nh], bl[nq][nh + 2]);   // AhBl
                    MMA_BF16(d, al[mf], bh[nq][nh], bh[nq][nh + 2]);   // AlBh
                }
    }
}

// ============================================================
// conv GEMM: E = relu( A_im2col @ W^T + b ), tiles 128x128, K=6144
// ============================================================
__global__ void __launch_bounds__(256, 1) conv_mma_kernel(
    const float* __restrict__ bias, float* __restrict__ E)
{
    extern __shared__ char smem[];
    const uint32_t sb = smem_u32(smem);
    const int tid  = threadIdx.x;
    const int wid  = tid >> 5;
    const int lane = tid & 31;
    const int bm = blockIdx.y * 128;
    const int bn = blockIdx.x * 128;
    const int wm = (wid >> 1) * 32;
    const int wn = (wid & 1) * 64;

    float acc[2][8][4];
#pragma unroll
    for (int i = 0; i < 2; i++)
#pragma unroll
        for (int j = 0; j < 8; j++)
#pragma unroll
            for (int c = 0; c < 4; c++) acc[i][j][c] = 0.f;

    const int CHUNKS = KC / 32;   // 192

    // ---- loader: chunk i -> stage (i&1) ----
    auto load_chunk = [&](int i) {
        const uint32_t st = sb + (i & 1) * STAGE;
        const int k0  = i * 32;
        const int seg = k0 >> 11;
        const int c0  = k0 & 2047;
        const int sh  = seg - 1;
#pragma unroll
        for (int it = 0; it < 2; it++) {
            const int slot = tid + it * 256;
            const int r = slot >> 2, sgm = slot & 3;
            const uint32_t dsto = r * PITCH + sgm * 16;
            // A (im2col)
            {
                const int gm = bm + r;
                const int sn = (gm & (NSEQ - 1)) + sh;
                const int ok = (sn >= 0 && sn < NSEQ) ? 16 : 0;
                const size_t srow = ok ? (size_t)(gm + sh) : 0;
                const size_t off = srow * DIN + c0 + sgm * 8;
                CP_ASYNC16(st + OFF_AH + dsto, (const char*)(g_Xhi + off), ok);
                CP_ASYNC16(st + OFF_AL + dsto, (const char*)(g_Xlo + off), ok);
            }
            // B (weights, N x K row-major)
            {
                const size_t off = (size_t)(bn + r) * KC + k0 + sgm * 8;
                CP_ASYNC16(st + OFF_BH + dsto, (const char*)(g_Whi + off), 16);
                CP_ASYNC16(st + OFF_BL + dsto, (const char*)(g_Wlo + off), 16);
            }
        }
        CP_COMMIT();
    };

    load_chunk(0);
    for (int i = 0; i < CHUNKS; i++) {
        if (i + 1 < CHUNKS) { load_chunk(i + 1); CP_WAIT1(); }
        else                { CP_WAIT0(); }
        __syncthreads();
        mma_chunk(sb + (i & 1) * STAGE, acc, wm, wn, lane);
        __syncthreads();
    }

    // ---- epilogue: bias + relu; write E fp32 + bf16 hi/lo split ----
#pragma unroll
    for (int mf = 0; mf < 2; mf++) {
        const int row0 = bm + wm + mf * 16 + (lane >> 2);
#pragma unroll
        for (int nf = 0; nf < 8; nf++) {
            const int col = bn + wn + nf * 8 + (lane & 3) * 2;
            const float b0 = __ldg(&bias[col]), b1 = __ldg(&bias[col + 1]);
#pragma unroll
            for (int h = 0; h < 2; h++) {
                const int row = row0 + h * 8;
                const float v0 = fmaxf(acc[mf][nf][2 * h]     + b0, 0.f);
                const float v1 = fmaxf(acc[mf][nf][2 * h + 1] + b1, 0.f);
                *reinterpret_cast<float2*>(E + (size_t)row * DOUT + col) = make_float2(v0, v1);
                uint32_t h0, l0, h1, l1;
                split_bf16(v0, h0, l0);
                split_bf16(v1, h1, l1);
                *reinterpret_cast<uint32_t*>(g_Ehi + (size_t)row * DOUT + col) = h0 | (h1 << 16);
                *reinterpret_cast<uint32_t*>(g_Elo + (size_t)row * DOUT + col) = l0 | (l1 << 16);
            }
        }
    }
}

// ============================================================
// score GEMM: S = E @ keys^T, tiles 128x128, K=512
// ============================================================
__global__ void __launch_bounds__(256, 1) score_mma_kernel()
{
    extern __shared__ char smem[];
    const uint32_t sb = smem_u32(smem);
    const int tid  = threadIdx.x;
    const int wid  = tid >> 5;
    const int lane = tid & 31;
    const int bm = blockIdx.y * 128;
    const int bn = blockIdx.x * 128;
    const int wm = (wid >> 1) * 32;
    const int wn = (wid & 1) * 64;

    float acc[2][8][4];
#pragma unroll
    for (int i = 0; i < 2; i++)
#pragma unroll
        for (int j = 0; j < 8; j++)
#pragma unroll
            for (int c = 0; c < 4; c++) acc[i][j][c] = 0.f;

    const int CHUNKS = DOUT / 32;   // 16

    auto load_chunk = [&](int i) {
        const uint32_t st = sb + (i & 1) * STAGE;
        const int k0 = i * 32;
#pragma unroll
        for (int it = 0; it < 2; it++) {
            const int slot = tid + it * 256;
            const int r = slot >> 2, sgm = slot & 3;
            const uint32_t dsto = r * PITCH + sgm * 16;
            const size_t offa = (size_t)(bm + r) * DOUT + k0 + sgm * 8;
            CP_ASYNC16(st + OFF_AH + dsto, (const char*)(g_Ehi + offa), 16);
            CP_ASYNC16(st + OFF_AL + dsto, (const char*)(g_Elo + offa), 16);
            const size_t offb = (size_t)(bn + r) * DOUT + k0 + sgm * 8;
            CP_ASYNC16(st + OFF_BH + dsto, (const char*)(g_Khi + offb), 16);
            CP_ASYNC16(st + OFF_BL + dsto, (const char*)(g_Klo + offb), 16);
        }
        CP_COMMIT();
    };

    load_chunk(0);
    for (int i = 0; i < CHUNKS; i++) {
        if (i + 1 < CHUNKS) { load_chunk(i + 1); CP_WAIT1(); }
        else                { CP_WAIT0(); }
        __syncthreads();
        mma_chunk(sb + (i & 1) * STAGE, acc, wm, wn, lane);
        __syncthreads();
    }

#pragma unroll
    for (int mf = 0; mf < 2; mf++) {
        const int row0 = bm + wm + mf * 16 + (lane >> 2);
#pragma unroll
        for (int nf = 0; nf < 8; nf++) {
            const int col = bn + wn + nf * 8 + (lane & 3) * 2;
#pragma unroll
            for (int h = 0; h < 2; h++) {
                const int row = row0 + h * 8;
                *reinterpret_cast<float2*>(g_S + (size_t)row * NKEYS + col) =
                    make_float2(acc[mf][nf][2 * h], acc[mf][nf][2 * h + 1]);
            }
        }
    }
}

// ============================================================
// per-row stats on E: p_score, w1dot, qq
// ============================================================
__global__ void rowstats_kernel(const float* __restrict__ E,
                                const float* __restrict__ cls_w,
                                const float* __restrict__ cls_b,
                                const float* __restrict__ cls_mem_w,
                                float* __restrict__ p_out)
{
    const int row  = blockIdx.x * 8 + (threadIdx.x >> 5);
    const int lane = threadIdx.x & 31;
    const float* q = E + (size_t)row * DOUT;
    float d0 = 0.f, d1 = 0.f, qq = 0.f;
#pragma unroll
    for (int t = 0; t < 4; t++) {
        const int c = (lane + t * 32) * 4;
        float4 v  = *reinterpret_cast<const float4*>(q + c);
        float4 w0 = *reinterpret_cast<const float4*>(cls_w + c);
        float4 w1 = *reinterpret_cast<const float4*>(cls_mem_w + c);
        d0 += v.x * w0.x + v.y * w0.y + v.z * w0.z + v.w * w0.w;
        d1 += v.x * w1.x + v.y * w1.y + v.z * w1.z + v.w * w1.w;
        qq += v.x * v.x + v.y * v.y + v.z * v.z + v.w * v.w;
    }
#pragma unroll
    for (int o = 16; o; o >>= 1) {
        d0 += __shfl_xor_sync(0xffffffffu, d0, o);
        d1 += __shfl_xor_sync(0xffffffffu, d1, o);
        qq += __shfl_xor_sync(0xffffffffu, qq, o);
    }
    if (lane == 0) {
        p_out[row]   = 1.f / (1.f + __expf(-(d0 + cls_b[0])));
        g_w1dot[row] = d1;
        g_qq[row]    = qq;
    }
}

// ============================================================
// softmax / argmax reduction over S rows -> up_score + both losses
// ============================================================
__global__ void softmax_reduce_kernel(const float* __restrict__ cls_mem_b,
                                      float* __restrict__ up_out,
                                      float* __restrict__ nor_out,
                                      float* __restrict__ abn_out)
{
    const int row  = blockIdx.x * 8 + (threadIdx.x >> 5);
    const int lane = threadIdx.x & 31;
    const float* Sr = g_S + (size_t)row * NKEYS;

    float s[32];
    float m = -INFINITY;
    float bv0 = -INFINITY, bv1 = -INFINITY;
    int bi0 = 0, bi1 = 0;
#pragma unroll
    for (int t = 0; t < 32; t++) {
        const int j = t * 32 + lane;
        const float v = Sr[j];
        s[t] = v;
        m = fmaxf(m, v);
        if (t < 16) { if (v > bv0) { bv0 = v; bi0 = j; } }
        else        { if (v > bv1) { bv1 = v; bi1 = j; } }
    }
#pragma unroll
    for (int o = 16; o; o >>= 1) m = fmaxf(m, __shfl_xor_sync(0xffffffffu, m, o));

    float l = 0.f, dsum = 0.f;
#pragma unroll
    for (int t = 0; t < 32; t++) {
        const int j = t * 32 + lane;
        const float e = __expf(s[t] - m);
        l += e;
        dsum += e * g_kv[j];
    }
#pragma unroll
    for (int o = 16; o; o >>= 1) {
        l    += __shfl_xor_sync(0xffffffffu, l, o);
        dsum += __shfl_xor_sync(0xffffffffu, dsum, o);
    }
#pragma unroll
    for (int o = 16; o; o >>= 1) {
        const float o0 = __shfl_xor_sync(0xffffffffu, bv0, o);
        const int   i0 = __shfl_xor_sync(0xffffffffu, bi0, o);
        if (o0 > bv0 || (o0 == bv0 && i0 < bi0)) { bv0 = o0; bi0 = i0; }
        const float o1 = __shfl_xor_sync(0xffffffffu, bv1, o);
        const int   i1 = __shfl_xor_sync(0xffffffffu, bi1, o);
        if (o1 > bv1 || (o1 == bv1 && i1 < bi1)) { bv1 = o1; bi1 = i1; }
    }
    if (lane == 0) {
        const float x = g_w1dot[row] + dsum / l + cls_mem_b[0];
        up_out[row] = 1.f / (1.f + __expf(-x));
        const float qq = g_qq[row];
        nor_out[row] = (qq - 2.f * bv0 + g_kkn[bi0]) * (1.f / 512.f);
        abn_out[row] = (qq - 2.f * bv1 + g_kkn[bi1]) * (1.f / 512.f);
    }
}

// ============================================================
// launch
// ============================================================
extern "C" void kernel_launch(void* const* d_in, const int* in_sizes, int n_in,
                              void* d_out, int out_size)
{
    const float* ref_nor   = (const float*)d_in[0];
    // d_in[1] = ref_abn : dead (only feeds the discarded p_score[B:])
    const float* nor_keys  = (const float*)d_in[2];
    const float* abn_keys  = (const float*)d_in[3];
    const float* conv_w    = (const float*)d_in[4];
    const float* conv_b    = (const float*)d_in[5];
    const float* cls_w     = (const float*)d_in[6];
    const float* cls_b     = (const float*)d_in[7];
    const float* cls_mem_w = (const float*)d_in[8];
    const float* cls_mem_b = (const float*)d_in[9];

    float* out      = (float*)d_out;
    float* p_score  = out;
    float* up_score = out + ROWS;
    float* nor_loss = out + 2 * ROWS;
    float* abn_loss = out + 3 * ROWS;
    float* E        = out + 4 * ROWS;

    cudaFuncSetAttribute(conv_mma_kernel,  cudaFuncAttributeMaxDynamicSharedMemorySize, SMEM_BYTES);
    cudaFuncSetAttribute(score_mma_kernel, cudaFuncAttributeMaxDynamicSharedMemorySize, SMEM_BYTES);

    convert_x_kernel<<<8192, 256>>>(ref_nor);
    convert_w_kernel<<<12288, 256>>>(conv_w);
    convert_keys_kernel<<<512, 256>>>(nor_keys, abn_keys);
    prep_keys_kernel<<<128, 256>>>(nor_keys, abn_keys, cls_mem_w);

    conv_mma_kernel<<<dim3(4, 64), 256, SMEM_BYTES>>>(conv_b, E);
    rowstats_kernel<<<1024, 256>>>(E, cls_w, cls_b, cls_mem_w, p_score);
    score_mma_kernel<<<dim3(8, 64), 256, SMEM_BYTES>>>();
    softmax_reduce_kernel<<<1024, 256>>>(cls_mem_b, up_score, nor_loss, abn_loss);
}

// round 4
// speedup vs baseline: 2.9431x; 1.3901x over previous
#include <cuda.h>
#include <cuda_runtime.h>
#include <cuda_bf16.h>
#include <math.h>
#include <stdint.h>

// Problem constants (B=32, N=256, D=2048, d=512, M=512)
#define ROWS  8192      // B*N
#define DIN   2048      // D
#define DOUT  512       // d
#define KC    6144      // 3*D (im2col K)
#define NKEYS 1024      // 2*M
#define NSEQ  256       // N

// ---------------- scratch (device globals; no allocation allowed) ----------------
__device__ __align__(1024) __nv_bfloat16 g_Xhi[ROWS * DIN];
__device__ __align__(1024) __nv_bfloat16 g_Xlo[ROWS * DIN];
__device__ __align__(1024) __nv_bfloat16 g_Whi[DOUT * KC];   // [o][seg*2048+c]
__device__ __align__(1024) __nv_bfloat16 g_Wlo[DOUT * KC];
__device__ __align__(1024) __nv_bfloat16 g_Ehi[ROWS * DOUT];
__device__ __align__(1024) __nv_bfloat16 g_Elo[ROWS * DOUT];
__device__ __align__(1024) __nv_bfloat16 g_Khi[NKEYS * DOUT];
__device__ __align__(1024) __nv_bfloat16 g_Klo[NKEYS * DOUT];
__device__ float g_S[(size_t)ROWS * NKEYS];
__device__ float g_kv[NKEYS];
__device__ float g_kkn[NKEYS];
__device__ float g_w1dot[ROWS];
__device__ float g_qq[ROWS];

// ---------------- device helpers ----------------
__device__ __forceinline__ uint32_t smem_u32(const void* p) {
    uint32_t a;
    asm("{ .reg .u64 t; cvta.to.shared.u64 t, %1; cvt.u32.u64 %0, t; }" : "=r"(a) : "l"(p));
    return a;
}

#define MBARRIER_INIT(addr, cnt) \
    asm volatile("mbarrier.init.shared.b64 [%0], %1;" :: "r"((uint32_t)(addr)), "r"((uint32_t)(cnt)) : "memory")
#define MBARRIER_EXPECT_TX(addr, bytes) \
    asm volatile("mbarrier.arrive.expect_tx.shared.b64 _, [%0], %1;" :: "r"((uint32_t)(addr)), "r"((uint32_t)(bytes)) : "memory")
#define MBARRIER_WAIT_PARITY(addr, parity) do {                                        \
    uint32_t _m = (uint32_t)(addr); uint32_t _p = (uint32_t)(parity); uint32_t _d;     \
    asm volatile("{\n\t.reg .pred p;\n\t"                                              \
        "mbarrier.try_wait.parity.acquire.cta.shared::cta.b64 p, [%1], %2;\n\t"        \
        "selp.b32 %0, 1, 0, p;\n\t}"                                                   \
        : "=r"(_d) : "r"(_m), "r"(_p) : "memory");                                     \
    if (!_d) {                                                                         \
        asm volatile("{\n\t.reg .pred P1;\n\t"                                         \
            "WL_%=:\n\t"                                                               \
            "mbarrier.try_wait.parity.acquire.cta.shared::cta.b64 P1, [%0], %1, 0x989680;\n\t" \
            "@P1 bra.uni WD_%=;\n\t"                                                   \
            "bra.uni WL_%=;\n\t"                                                       \
            "WD_%=:\n\t}"                                                              \
            :: "r"(_m), "r"(_p) : "memory");                                           \
    }                                                                                  \
} while (0)

#define TMA_2D(smaddr, map, x, y, mbar) \
    asm volatile("cp.async.bulk.tensor.2d.shared::cta.global.tile.mbarrier::complete_tx::bytes " \
                 "[%0], [%1, {%2, %3}], [%4];" \
                 :: "r"((uint32_t)(smaddr)), "l"(map), "r"((int)(x)), "r"((int)(y)), \
                    "r"((uint32_t)(mbar)) : "memory")

#define LDMATRIX_X4(r0, r1, r2, r3, addr) \
    asm volatile("ldmatrix.sync.aligned.m8n8.x4.shared.b16 {%0,%1,%2,%3}, [%4];" \
                 : "=r"(r0), "=r"(r1), "=r"(r2), "=r"(r3) : "r"(addr))

#define MMA_BF16(d, a, b0v, b1v) \
    asm volatile("mma.sync.aligned.m16n8k16.row.col.f32.bf16.bf16.f32 " \
                 "{%0,%1,%2,%3}, {%4,%5,%6,%7}, {%8,%9}, {%0,%1,%2,%3};" \
                 : "+f"((d)[0]), "+f"((d)[1]), "+f"((d)[2]), "+f"((d)[3]) \
                 : "r"((a)[0]), "r"((a)[1]), "r"((a)[2]), "r"((a)[3]), \
                   "r"(b0v), "r"(b1v))

__device__ __forceinline__ void split_bf16(float x, uint32_t& h, uint32_t& l) {
    __nv_bfloat16 hb = __float2bfloat16(x);
    float hf = __bfloat162float(hb);
    __nv_bfloat16 lb = __float2bfloat16(x - hf);
    h = (uint32_t)__bfloat16_as_ushort(hb);
    l = (uint32_t)__bfloat16_as_ushort(lb);
}

#define SW128(b) ((b) ^ (((b) >> 3) & 0x70))

// SMEM layout: barriers at [0,24), stages at 1024 + s*65536.
// Stage matrices: AH +0, AL +16384, BH +32768, BL +49152 (each 128 rows x 128B, SW128).
#define STG_BASE   1024
#define STG_BYTES  65536
#define M_AH 0
#define M_AL 16384
#define M_BH 32768
#define M_BL 49152
#define NSTAGE 3
#define SMEM_BYTES (STG_BASE + NSTAGE * STG_BYTES)   // 197632

// ============================================================
// conversions
// ============================================================
__global__ void convert_x_kernel(const float* __restrict__ X) {
    size_t base = ((size_t)blockIdx.x * 256 + threadIdx.x) * 8;
    float4 v0 = *reinterpret_cast<const float4*>(X + base);
    float4 v1 = *reinterpret_cast<const float4*>(X + base + 4);
    float f[8] = {v0.x, v0.y, v0.z, v0.w, v1.x, v1.y, v1.z, v1.w};
    uint32_t hw[4], lw[4];
#pragma unroll
    for (int c = 0; c < 4; c++) {
        uint32_t h0, l0, h1, l1;
        split_bf16(f[2 * c], h0, l0);
        split_bf16(f[2 * c + 1], h1, l1);
        hw[c] = h0 | (h1 << 16);
        lw[c] = l0 | (l1 << 16);
    }
    *reinterpret_cast<uint4*>(g_Xhi + base) = make_uint4(hw[0], hw[1], hw[2], hw[3]);
    *reinterpret_cast<uint4*>(g_Xlo + base) = make_uint4(lw[0], lw[1], lw[2], lw[3]);
}

__global__ void convert_w_kernel(const float* __restrict__ conv_w) {
    int idx = blockIdx.x * 256 + threadIdx.x;     // 0 .. 512*6144-1
    int o = idx / KC;
    int kk = idx - o * KC;
    int seg = kk >> 11;
    int c = kk & 2047;
    float v = conv_w[(size_t)o * KC + c * 3 + seg];
    uint32_t h, l;
    split_bf16(v, h, l);
    g_Whi[idx] = __ushort_as_bfloat16((unsigned short)h);
    g_Wlo[idx] = __ushort_as_bfloat16((unsigned short)l);
}

__global__ void convert_keys_kernel(const float* __restrict__ nor_keys,
                                    const float* __restrict__ abn_keys) {
    size_t e = ((size_t)blockIdx.x * 256 + threadIdx.x) * 4;
    int j = (int)(e >> 9);
    int col = (int)(e & 511);
    const float* src = (j < 512) ? (nor_keys + (size_t)j * DOUT + col)
                                 : (abn_keys + (size_t)(j - 512) * DOUT + col);
    float4 v = *reinterpret_cast<const float4*>(src);
    uint32_t h0, l0, h1, l1, h2, l2, h3, l3;
    split_bf16(v.x, h0, l0); split_bf16(v.y, h1, l1);
    split_bf16(v.z, h2, l2); split_bf16(v.w, h3, l3);
    *reinterpret_cast<uint2*>(g_Khi + e) = make_uint2(h0 | (h1 << 16), h2 | (h3 << 16));
    *reinterpret_cast<uint2*>(g_Klo + e) = make_uint2(l0 | (l1 << 16), l2 | (l3 << 16));
}

__global__ void prep_keys_kernel(const float* __restrict__ nor_keys,
                                 const float* __restrict__ abn_keys,
                                 const float* __restrict__ cls_mem_w) {
    const int j = blockIdx.x * 8 + (threadIdx.x >> 5);
    const int lane = threadIdx.x & 31;
    const float* key = (j < 512) ? (nor_keys + (size_t)j * DOUT)
                                 : (abn_keys + (size_t)(j - 512) * DOUT);
    const float* w2 = cls_mem_w + DOUT;
    float kv = 0.f, kn = 0.f;
#pragma unroll
    for (int t = 0; t < 4; t++) {
        const int c = (lane + t * 32) * 4;
        float4 k4 = *reinterpret_cast<const float4*>(key + c);
        float4 w4 = *reinterpret_cast<const float4*>(w2 + c);
        kv += k4.x * w4.x + k4.y * w4.y + k4.z * w4.z + k4.w * w4.w;
        kn += k4.x * k4.x + k4.y * k4.y + k4.z * k4.z + k4.w * k4.w;
    }
#pragma unroll
    for (int o = 16; o; o >>= 1) {
        kv += __shfl_xor_sync(0xffffffffu, kv, o);
        kn += __shfl_xor_sync(0xffffffffu, kn, o);
    }
    if (lane == 0) { g_kv[j] = kv; g_kkn[j] = kn; }
}

// ============================================================
// 3-pass bf16 MMA over one 128x128x64 chunk in SW128 SMEM
// 8 warps as 4(M)x2(N): warp tile 32x64.
// ============================================================
__device__ __forceinline__ void mma_chunk_sw(uint32_t st, float acc[2][8][4],
                                             int wm, int wn, int lane)
{
    const int lrow  = lane & 15;
    const int khalf = lane >> 4;
#pragma unroll
    for (int ks = 0; ks < 4; ks++) {
        const uint32_t kb = ks * 32 + khalf * 16;
        uint32_t ah[2][4], al[2][4];
#pragma unroll
        for (int mf = 0; mf < 2; mf++) {
            const uint32_t ro = (uint32_t)((wm + mf * 16 + lrow) * 128) + kb;
            LDMATRIX_X4(ah[mf][0], ah[mf][1], ah[mf][2], ah[mf][3], st + M_AH + SW128(ro));
            LDMATRIX_X4(al[mf][0], al[mf][1], al[mf][2], al[mf][3], st + M_AL + SW128(ro));
        }
        uint32_t bh[4][4], bl[4][4];
#pragma unroll
        for (int nq = 0; nq < 4; nq++) {
            const uint32_t ro = (uint32_t)((wn + nq * 16 + lrow) * 128) + kb;
            LDMATRIX_X4(bh[nq][0], bh[nq][1], bh[nq][2], bh[nq][3], st + M_BH + SW128(ro));
            LDMATRIX_X4(bl[nq][0], bl[nq][1], bl[nq][2], bl[nq][3], st + M_BL + SW128(ro));
        }
#pragma unroll
        for (int mf = 0; mf < 2; mf++)
#pragma unroll
            for (int nq = 0; nq < 4; nq++)
#pragma unroll
                for (int nh = 0; nh < 2; nh++) {
                    float* d = acc[mf][nq * 2 + nh];
                    MMA_BF16(d, ah[mf], bh[nq][nh], bh[nq][nh + 2]);   // AhBh
                    MMA_BF16(d, ah[mf], bl[nq][nh], bl[nq][nh + 2]);   // AhBl
                    MMA_BF16(d, al[mf], bh[nq][nh], bh[nq][nh + 2]);   // AlBh
                }
    }
}

// ============================================================
// conv GEMM: E = relu( A_im2col @ W^T + b ), tile 128x128, K=6144, TMA feed
// ============================================================
__global__ void __launch_bounds__(256, 1) conv_mma_kernel(
    const __grid_constant__ CUtensorMap mXh,
    const __grid_constant__ CUtensorMap mXl,
    const __grid_constant__ CUtensorMap mWh,
    const __grid_constant__ CUtensorMap mWl,
    const float* __restrict__ bias, float* __restrict__ E)
{
    extern __shared__ char smem[];
    const uint32_t sb = smem_u32(smem);
    const int tid  = threadIdx.x;
    const int wid  = tid >> 5;
    const int lane = tid & 31;
    const int bm = blockIdx.y * 128;
    const int bn = blockIdx.x * 128;
    const int wm = (wid >> 1) * 32;
    const int wn = (wid & 1) * 64;
    const int evenTile = ((bm & 255) == 0);

    float acc[2][8][4];
#pragma unroll
    for (int i = 0; i < 2; i++)
#pragma unroll
        for (int j = 0; j < 8; j++)
#pragma unroll
            for (int c = 0; c < 4; c++) acc[i][j][c] = 0.f;

    if (tid == 0) {
        MBARRIER_INIT(sb + 0, 1);
        MBARRIER_INIT(sb + 8, 1);
        MBARRIER_INIT(sb + 16, 1);
    }
    __syncthreads();

    const int CHUNKS = KC / 64;   // 96
    auto issue = [&](int i) {
        const int s = i % NSTAGE;
        const uint32_t st = sb + STG_BASE + s * STG_BYTES;
        const uint32_t mb = sb + s * 8;
        const int k0 = i * 64;
        const int seg = k0 >> 11;
        const int c0 = k0 & 2047;
        MBARRIER_EXPECT_TX(mb, STG_BYTES);
        TMA_2D(st + M_AH, &mXh, c0, bm + seg - 1, mb);
        TMA_2D(st + M_AL, &mXl, c0, bm + seg - 1, mb);
        TMA_2D(st + M_BH, &mWh, k0, bn, mb);
        TMA_2D(st + M_BL, &mWl, k0, bn, mb);
    };
    if (tid == 0) { issue(0); issue(1); issue(2); }

    for (int i = 0; i < CHUNKS; i++) {
        const int s = i % NSTAGE;
        MBARRIER_WAIT_PARITY(sb + s * 8, (uint32_t)((i / NSTAGE) & 1));
        // zero-fix interior sequence-boundary rows (TMA loaded neighbor-seq data)
        const int seg = i >> 5;     // i*64 >> 11
        int fr = -1;
        if (seg == 0 && evenTile) fr = 0;
        else if (seg == 2 && !evenTile) fr = 127;
        if (fr >= wm && fr < wm + 32) {
            char* stp = smem + STG_BASE + s * STG_BYTES;
            *reinterpret_cast<uint32_t*>(stp + M_AH + fr * 128 + lane * 4) = 0u;
            *reinterpret_cast<uint32_t*>(stp + M_AL + fr * 128 + lane * 4) = 0u;
        }
        __syncwarp();
        mma_chunk_sw(sb + STG_BASE + s * STG_BYTES, acc, wm, wn, lane);
        __syncthreads();
        if (tid == 0 && i + NSTAGE < CHUNKS) issue(i + NSTAGE);
    }

    // epilogue: bias + relu; write E fp32 + bf16 hi/lo split
#pragma unroll
    for (int mf = 0; mf < 2; mf++) {
        const int row0 = bm + wm + mf * 16 + (lane >> 2);
#pragma unroll
        for (int nf = 0; nf < 8; nf++) {
            const int col = bn + wn + nf * 8 + (lane & 3) * 2;
            const float b0 = __ldg(&bias[col]), b1 = __ldg(&bias[col + 1]);
#pragma unroll
            for (int h = 0; h < 2; h++) {
                const int row = row0 + h * 8;
                const float v0 = fmaxf(acc[mf][nf][2 * h]     + b0, 0.f);
                const float v1 = fmaxf(acc[mf][nf][2 * h + 1] + b1, 0.f);
                *reinterpret_cast<float2*>(E + (size_t)row * DOUT + col) = make_float2(v0, v1);
                uint32_t h0, l0, h1, l1;
                split_bf16(v0, h0, l0);
                split_bf16(v1, h1, l1);
                *reinterpret_cast<uint32_t*>(g_Ehi + (size_t)row * DOUT + col) = h0 | (h1 << 16);
                *reinterpret_cast<uint32_t*>(g_Elo + (size_t)row * DOUT + col) = l0 | (l1 << 16);
            }
        }
    }
}

// ============================================================
// score GEMM: S = E @ keys^T, tile 128x128, K=512, TMA feed
// ============================================================
__global__ void __launch_bounds__(256, 1) score_mma_kernel(
    const __grid_constant__ CUtensorMap mEh,
    const __grid_constant__ CUtensorMap mEl,
    const __grid_constant__ CUtensorMap mKh,
    const __grid_constant__ CUtensorMap mKl)
{
    extern __shared__ char smem[];
    const uint32_t sb = smem_u32(smem);
    const int tid  = threadIdx.x;
    const int wid  = tid >> 5;
    const int lane = tid & 31;
    const int bm = blockIdx.y * 128;
    const int bn = blockIdx.x * 128;
    const int wm = (wid >> 1) * 32;
    const int wn = (wid & 1) * 64;

    float acc[2][8][4];
#pragma unroll
    for (int i = 0; i < 2; i++)
#pragma unroll
        for (int j = 0; j < 8; j++)
#pragma unroll
            for (int c = 0; c < 4; c++) acc[i][j][c] = 0.f;

    if (tid == 0) {
        MBARRIER_INIT(sb + 0, 1);
        MBARRIER_INIT(sb + 8, 1);
        MBARRIER_INIT(sb + 16, 1);
    }
    __syncthreads();

    const int CHUNKS = DOUT / 64;   // 8
    auto issue = [&](int i) {
        const int s = i % NSTAGE;
        const uint32_t st = sb + STG_BASE + s * STG_BYTES;
        const uint32_t mb = sb + s * 8;
        const int k0 = i * 64;
        MBARRIER_EXPECT_TX(mb, STG_BYTES);
        TMA_2D(st + M_AH, &mEh, k0, bm, mb);
        TMA_2D(st + M_AL, &mEl, k0, bm, mb);
        TMA_2D(st + M_BH, &mKh, k0, bn, mb);
        TMA_2D(st + M_BL, &mKl, k0, bn, mb);
    };
    if (tid == 0) { issue(0); issue(1); issue(2); }

    for (int i = 0; i < CHUNKS; i++) {
        const int s = i % NSTAGE;
        MBARRIER_WAIT_PARITY(sb + s * 8, (uint32_t)((i / NSTAGE) & 1));
        mma_chunk_sw(sb + STG_BASE + s * STG_BYTES, acc, wm, wn, lane);
        __syncthreads();
        if (tid == 0 && i + NSTAGE < CHUNKS) issue(i + NSTAGE);
    }

#pragma unroll
    for (int mf = 0; mf < 2; mf++) {
        const int row0 = bm + wm + mf * 16 + (lane >> 2);
#pragma unroll
        for (int nf = 0; nf < 8; nf++) {
            const int col = bn + wn + nf * 8 + (lane & 3) * 2;
#pragma unroll
            for (int h = 0; h < 2; h++) {
                const int row = row0 + h * 8;
                *reinterpret_cast<float2*>(g_S + (size_t)row * NKEYS + col) =
                    make_float2(acc[mf][nf][2 * h], acc[mf][nf][2 * h + 1]);
            }
        }
    }
}

// ============================================================
// per-row stats on E: p_score, w1dot, qq
// ============================================================
__global__ void rowstats_kernel(const float* __restrict__ E,
                                const float* __restrict__ cls_w,
                                const float* __restrict__ cls_b,
                                const float* __restrict__ cls_mem_w,
                                float* __restrict__ p_out)
{
    const int row  = blockIdx.x * 8 + (threadIdx.x >> 5);
    const int lane = threadIdx.x & 31;
    const float* q = E + (size_t)row * DOUT;
    float d0 = 0.f, d1 = 0.f, qq = 0.f;
#pragma unroll
    for (int t = 0; t < 4; t++) {
        const int c = (lane + t * 32) * 4;
        float4 v  = *reinterpret_cast<const float4*>(q + c);
        float4 w0 = *reinterpret_cast<const float4*>(cls_w + c);
        float4 w1 = *reinterpret_cast<const float4*>(cls_mem_w + c);
        d0 += v.x * w0.x + v.y * w0.y + v.z * w0.z + v.w * w0.w;
        d1 += v.x * w1.x + v.y * w1.y + v.z * w1.z + v.w * w1.w;
        qq += v.x * v.x + v.y * v.y + v.z * v.z + v.w * v.w;
    }
#pragma unroll
    for (int o = 16; o; o >>= 1) {
        d0 += __shfl_xor_sync(0xffffffffu, d0, o);
        d1 += __shfl_xor_sync(0xffffffffu, d1, o);
        qq += __shfl_xor_sync(0xffffffffu, qq, o);
    }
    if (lane == 0) {
        p_out[row]   = 1.f / (1.f + __expf(-(d0 + cls_b[0])));
        g_w1dot[row] = d1;
        g_qq[row]    = qq;
    }
}

// ============================================================
// softmax / argmax reduction over S rows
// ============================================================
__global__ void softmax_reduce_kernel(const float* __restrict__ cls_mem_b,
                                      float* __restrict__ up_out,
                                      float* __restrict__ nor_out,
                                      float* __restrict__ abn_out)
{
    const int row  = blockIdx.x * 8 + (threadIdx.x >> 5);
    const int lane = threadIdx.x & 31;
    const float* Sr = g_S + (size_t)row * NKEYS;

    float s[32];
    float m = -INFINITY;
    float bv0 = -INFINITY, bv1 = -INFINITY;
    int bi0 = 0, bi1 = 0;
#pragma unroll
    for (int t = 0; t < 32; t++) {
        const int j = t * 32 + lane;
        const float v = Sr[j];
        s[t] = v;
        m = fmaxf(m, v);
        if (t < 16) { if (v > bv0) { bv0 = v; bi0 = j; } }
        else        { if (v > bv1) { bv1 = v; bi1 = j; } }
    }
#pragma unroll
    for (int o = 16; o; o >>= 1) m = fmaxf(m, __shfl_xor_sync(0xffffffffu, m, o));

    float l = 0.f, dsum = 0.f;
#pragma unroll
    for (int t = 0; t < 32; t++) {
        const int j = t * 32 + lane;
        const float e = __expf(s[t] - m);
        l += e;
        dsum += e * g_kv[j];
    }
#pragma unroll
    for (int o = 16; o; o >>= 1) {
        l    += __shfl_xor_sync(0xffffffffu, l, o);
        dsum += __shfl_xor_sync(0xffffffffu, dsum, o);
    }
#pragma unroll
    for (int o = 16; o; o >>= 1) {
        const float o0 = __shfl_xor_sync(0xffffffffu, bv0, o);
        const int   i0 = __shfl_xor_sync(0xffffffffu, bi0, o);
        if (o0 > bv0 || (o0 == bv0 && i0 < bi0)) { bv0 = o0; bi0 = i0; }
        const float o1 = __shfl_xor_sync(0xffffffffu, bv1, o);
        const int   i1 = __shfl_xor_sync(0xffffffffu, bi1, o);
        if (o1 > bv1 || (o1 == bv1 && i1 < bi1)) { bv1 = o1; bi1 = i1; }
    }
    if (lane == 0) {
        const float x = g_w1dot[row] + dsum / l + cls_mem_b[0];
        up_out[row] = 1.f / (1.f + __expf(-x));
        const float qq = g_qq[row];
        nor_out[row] = (qq - 2.f * bv0 + g_kkn[bi0]) * (1.f / 512.f);
        abn_out[row] = (qq - 2.f * bv1 + g_kkn[bi1]) * (1.f / 512.f);
    }
}

// ============================================================
// host: tensormap construction (driver entry point via cudart; no -lcuda)
// ============================================================
typedef CUresult (*PFN_tmEnc)(CUtensorMap*, CUtensorMapDataType, cuuint32_t, void*,
                              const cuuint64_t*, const cuuint64_t*, const cuuint32_t*,
                              const cuuint32_t*, CUtensorMapInterleave, CUtensorMapSwizzle,
                              CUtensorMapL2promotion, CUtensorMapFloatOOBfill);

static void enc2d(PFN_tmEnc f, CUtensorMap* m, void* addr,
                  unsigned long long d0, unsigned long long d1,
                  unsigned long long stride_bytes)
{
    cuuint64_t dims[2]    = {(cuuint64_t)d0, (cuuint64_t)d1};
    cuuint64_t strides[1] = {(cuuint64_t)stride_bytes};
    cuuint32_t box[2]     = {64u, 128u};
    cuuint32_t es[2]      = {1u, 1u};
    f(m, CU_TENSOR_MAP_DATA_TYPE_BFLOAT16, 2, addr, dims, strides, box, es,
      CU_TENSOR_MAP_INTERLEAVE_NONE, CU_TENSOR_MAP_SWIZZLE_128B,
      CU_TENSOR_MAP_L2_PROMOTION_L2_128B, CU_TENSOR_MAP_FLOAT_OOB_FILL_NONE);
}

extern "C" void kernel_launch(void* const* d_in, const int* in_sizes, int n_in,
                              void* d_out, int out_size)
{
    const float* ref_nor   = (const float*)d_in[0];
    // d_in[1] = ref_abn : dead (only feeds the discarded p_score[B:])
    const float* nor_keys  = (const float*)d_in[2];
    const float* abn_keys  = (const float*)d_in[3];
    const float* conv_w    = (const float*)d_in[4];
    const float* conv_b    = (const float*)d_in[5];
    const float* cls_w     = (const float*)d_in[6];
    const float* cls_b     = (const float*)d_in[7];
    const float* cls_mem_w = (const float*)d_in[8];
    const float* cls_mem_b = (const float*)d_in[9];

    float* out      = (float*)d_out;
    float* p_score  = out;
    float* up_score = out + ROWS;
    float* nor_loss = out + 2 * ROWS;
    float* abn_loss = out + 3 * ROWS;
    float* E        = out + 4 * ROWS;

    // tensormaps (host-built each call; capture-safe, no allocation)
    PFN_tmEnc enc = nullptr;
    cudaDriverEntryPointQueryResult qr;
    cudaGetDriverEntryPoint("cuTensorMapEncodeTiled", (void**)&enc,
                            cudaEnableDefault, &qr);
    void *pXh, *pXl, *pWh, *pWl, *pEh, *pEl, *pKh, *pKl;
    cudaGetSymbolAddress(&pXh, g_Xhi); cudaGetSymbolAddress(&pXl, g_Xlo);
    cudaGetSymbolAddress(&pWh, g_Whi); cudaGetSymbolAddress(&pWl, g_Wlo);
    cudaGetSymbolAddress(&pEh, g_Ehi); cudaGetSymbolAddress(&pEl, g_Elo);
    cudaGetSymbolAddress(&pKh, g_Khi); cudaGetSymbolAddress(&pKl, g_Klo);

    CUtensorMap mXh, mXl, mWh, mWl, mEh, mEl, mKh, mKl;
    enc2d(enc, &mXh, pXh, DIN,  ROWS,  (unsigned long long)DIN  * 2);
    enc2d(enc, &mXl, pXl, DIN,  ROWS,  (unsigned long long)DIN  * 2);
    enc2d(enc, &mWh, pWh, KC,   DOUT,  (unsigned long long)KC   * 2);
    enc2d(enc, &mWl, pWl, KC,   DOUT,  (unsigned long long)KC   * 2);
    enc2d(enc, &mEh, pEh, DOUT, ROWS,  (unsigned long long)DOUT * 2);
    enc2d(enc, &mEl, pEl, DOUT, ROWS,  (unsigned long long)DOUT * 2);
    enc2d(enc, &mKh, pKh, DOUT, NKEYS, (unsigned long long)DOUT * 2);
    enc2d(enc, &mKl, pKl, DOUT, NKEYS, (unsigned long long)DOUT * 2);

    cudaFuncSetAttribute(conv_mma_kernel,  cudaFuncAttributeMaxDynamicSharedMemorySize, SMEM_BYTES);
    cudaFuncSetAttribute(score_mma_kernel, cudaFuncAttributeMaxDynamicSharedMemorySize, SMEM_BYTES);

    convert_x_kernel<<<8192, 256>>>(ref_nor);
    convert_w_kernel<<<12288, 256>>>(conv_w);
    convert_keys_kernel<<<512, 256>>>(nor_keys, abn_keys);
    prep_keys_kernel<<<128, 256>>>(nor_keys, abn_keys, cls_mem_w);

    conv_mma_kernel<<<dim3(4, 64), 256, SMEM_BYTES>>>(mXh, mXl, mWh, mWl, conv_b, E);
    rowstats_kernel<<<1024, 256>>>(E, cls_w, cls_b, cls_mem_w, p_score);
    score_mma_kernel<<<dim3(8, 64), 256, SMEM_BYTES>>>(mEh, mEl, mKh, mKl);
    softmax_reduce_kernel<<<1024, 256>>>(cls_mem_b, up_score, nor_loss, abn_loss);
}

// round 5
// speedup vs baseline: 4.5116x; 1.5329x over previous
#include <cuda.h>
#include <cuda_runtime.h>
#include <cuda_bf16.h>
#include <math.h>
#include <stdint.h>

// Problem constants (B=32, N=256, D=2048, d=512, M=512)
#define ROWS  8192      // B*N
#define DIN   2048      // D
#define DOUT  512       // d
#define NKEYS 1024      // 2*M
#define NSEQ  256       // N
#define NTILE 64        // N/4 winograd tiles per sequence
#define GT    2048      // B*NTILE global tiles
#define NPTS  6         // winograd F(4,3) points

// ---------------- scratch (device globals; no allocation allowed) ----------------
__device__ __align__(1024) __nv_bfloat16 g_Uhi[NPTS * GT * DIN];     // 50MB
__device__ __align__(1024) __nv_bfloat16 g_Ulo[NPTS * GT * DIN];
__device__ __align__(1024) __nv_bfloat16 g_Vhi[NPTS * DOUT * DIN];   // 12.6MB
__device__ __align__(1024) __nv_bfloat16 g_Vlo[NPTS * DOUT * DIN];
__device__ float g_M[(size_t)NPTS * GT * DOUT];                      // 25MB
__device__ __align__(1024) __nv_bfloat16 g_Ehi[ROWS * DOUT];
__device__ __align__(1024) __nv_bfloat16 g_Elo[ROWS * DOUT];
__device__ __align__(1024) __nv_bfloat16 g_Khi[NKEYS * DOUT];
__device__ __align__(1024) __nv_bfloat16 g_Klo[NKEYS * DOUT];
__device__ float g_S[(size_t)ROWS * NKEYS];
__device__ float g_kv[NKEYS];
__device__ float g_kkn[NKEYS];
__device__ float g_w1dot[ROWS];
__device__ float g_qq[ROWS];

// ---------------- device helpers ----------------
__device__ __forceinline__ uint32_t smem_u32(const void* p) {
    uint32_t a;
    asm("{ .reg .u64 t; cvta.to.shared.u64 t, %1; cvt.u32.u64 %0, t; }" : "=r"(a) : "l"(p));
    return a;
}

#define MBARRIER_INIT(addr, cnt) \
    asm volatile("mbarrier.init.shared.b64 [%0], %1;" :: "r"((uint32_t)(addr)), "r"((uint32_t)(cnt)) : "memory")
#define MBARRIER_EXPECT_TX(addr, bytes) \
    asm volatile("mbarrier.arrive.expect_tx.shared.b64 _, [%0], %1;" :: "r"((uint32_t)(addr)), "r"((uint32_t)(bytes)) : "memory")
#define MBARRIER_WAIT_PARITY(addr, parity) do {                                        \
    uint32_t _m = (uint32_t)(addr); uint32_t _p = (uint32_t)(parity); uint32_t _d;     \
    asm volatile("{\n\t.reg .pred p;\n\t"                                              \
        "mbarrier.try_wait.parity.acquire.cta.shared::cta.b64 p, [%1], %2;\n\t"        \
        "selp.b32 %0, 1, 0, p;\n\t}"                                                   \
        : "=r"(_d) : "r"(_m), "r"(_p) : "memory");                                     \
    if (!_d) {                                                                         \
        asm volatile("{\n\t.reg .pred P1;\n\t"                                         \
            "WL_%=:\n\t"                                                               \
            "mbarrier.try_wait.parity.acquire.cta.shared::cta.b64 P1, [%0], %1, 0x989680;\n\t" \
            "@P1 bra.uni WD_%=;\n\t"                                                   \
            "bra.uni WL_%=;\n\t"                                                       \
            "WD_%=:\n\t}"                                                              \
            :: "r"(_m), "r"(_p) : "memory");                                           \
    }                                                                                  \
} while (0)

#define TMA_2D(smaddr, map, x, y, mbar) \
    asm volatile("cp.async.bulk.tensor.2d.shared::cta.global.tile.mbarrier::complete_tx::bytes " \
                 "[%0], [%1, {%2, %3}], [%4];" \
                 :: "r"((uint32_t)(smaddr)), "l"(map), "r"((int)(x)), "r"((int)(y)), \
                    "r"((uint32_t)(mbar)) : "memory")

#define LDMATRIX_X4(r0, r1, r2, r3, addr) \
    asm volatile("ldmatrix.sync.aligned.m8n8.x4.shared.b16 {%0,%1,%2,%3}, [%4];" \
                 : "=r"(r0), "=r"(r1), "=r"(r2), "=r"(r3) : "r"(addr))

#define MMA_BF16(d, a, b0v, b1v) \
    asm volatile("mma.sync.aligned.m16n8k16.row.col.f32.bf16.bf16.f32 " \
                 "{%0,%1,%2,%3}, {%4,%5,%6,%7}, {%8,%9}, {%0,%1,%2,%3};" \
                 : "+f"((d)[0]), "+f"((d)[1]), "+f"((d)[2]), "+f"((d)[3]) \
                 : "r"((a)[0]), "r"((a)[1]), "r"((a)[2]), "r"((a)[3]), \
                   "r"(b0v), "r"(b1v))

__device__ __forceinline__ void split_bf16(float x, uint32_t& h, uint32_t& l) {
    __nv_bfloat16 hb = __float2bfloat16(x);
    float hf = __bfloat162float(hb);
    __nv_bfloat16 lb = __float2bfloat16(x - hf);
    h = (uint32_t)__bfloat16_as_ushort(hb);
    l = (uint32_t)__bfloat16_as_ushort(lb);
}

#define SW128(b) ((b) ^ (((b) >> 3) & 0x70))

// SMEM: barriers [0,24), stages at 1024 + s*65536. Matrices: AH, AL, BH, BL (16KB each).
#define STG_BASE   1024
#define STG_BYTES  65536
#define M_AH 0
#define M_AL 16384
#define M_BH 32768
#define M_BL 49152
#define NSTAGE 3
#define SMEM_BYTES (STG_BASE + NSTAGE * STG_BYTES)   // 197632

// ============================================================
// Winograd F(4,3) input transform: X -> U_p (bf16 hi/lo), p=0..5
// u = BT d, d[i] = x[b, 4t-1+i, c]
// ============================================================
__global__ void wino_input_kernel(const float* __restrict__ X)
{
    const int gt = blockIdx.x;          // b*64 + t
    const int b = gt >> 6, t = gt & 63;
    const int n0 = 4 * t - 1;
#pragma unroll
    for (int cc = 0; cc < 8; cc++) {
        const int c = threadIdx.x + cc * 256;
        float d[6];
#pragma unroll
        for (int i = 0; i < 6; i++) {
            const int n = n0 + i;
            d[i] = (n >= 0 && n < NSEQ) ? X[((size_t)b * NSEQ + n) * DIN + c] : 0.f;
        }
        float u[6];
        u[0] =  4.f * d[0] - 5.f * d[2] + d[4];
        u[1] = -4.f * (d[1] + d[2]) + d[3] + d[4];
        u[2] =  4.f * d[1] - 4.f * d[2] - d[3] + d[4];
        u[3] = -2.f * d[1] - d[2] + 2.f * d[3] + d[4];
        u[4] =  2.f * d[1] - d[2] - 2.f * d[3] + d[4];
        u[5] =  4.f * d[1] - 5.f * d[3] + d[5];
#pragma unroll
        for (int p = 0; p < 6; p++) {
            uint32_t h, l;
            split_bf16(u[p], h, l);
            const size_t off = ((size_t)(p * GT + gt)) * DIN + c;
            g_Uhi[off] = __ushort_as_bfloat16((unsigned short)h);
            g_Ulo[off] = __ushort_as_bfloat16((unsigned short)l);
        }
    }
}

// ============================================================
// Winograd weight transform: conv_w (o, c, 3) -> V_p[o][c] = (G w)_p
// ============================================================
__global__ void wino_weight_kernel(const float* __restrict__ conv_w)
{
    const int idx = blockIdx.x * 256 + threadIdx.x;   // o*2048 + c
    const float w0 = conv_w[3 * (size_t)idx + 0];
    const float w1 = conv_w[3 * (size_t)idx + 1];
    const float w2 = conv_w[3 * (size_t)idx + 2];
    float v[6];
    v[0] =  0.25f * w0;
    v[1] = -(w0 + w1 + w2) * (1.f / 6.f);
    v[2] = (-w0 + w1 - w2) * (1.f / 6.f);
    v[3] =  w0 * (1.f / 24.f) + w1 * (1.f / 12.f) + w2 * (1.f / 6.f);
    v[4] =  w0 * (1.f / 24.f) - w1 * (1.f / 12.f) + w2 * (1.f / 6.f);
    v[5] =  w2;
    const int o = idx >> 11, c = idx & 2047;
#pragma unroll
    for (int p = 0; p < 6; p++) {
        uint32_t h, l;
        split_bf16(v[p], h, l);
        const size_t off = ((size_t)(p * DOUT + o)) * DIN + c;
        g_Vhi[off] = __ushort_as_bfloat16((unsigned short)h);
        g_Vlo[off] = __ushort_as_bfloat16((unsigned short)l);
    }
}

// ============================================================
// keys -> bf16 hi/lo (concat nor|abn)
// ============================================================
__global__ void convert_keys_kernel(const float* __restrict__ nor_keys,
                                    const float* __restrict__ abn_keys) {
    size_t e = ((size_t)blockIdx.x * 256 + threadIdx.x) * 4;
    int j = (int)(e >> 9);
    int col = (int)(e & 511);
    const float* src = (j < 512) ? (nor_keys + (size_t)j * DOUT + col)
                                 : (abn_keys + (size_t)(j - 512) * DOUT + col);
    float4 v = *reinterpret_cast<const float4*>(src);
    uint32_t h0, l0, h1, l1, h2, l2, h3, l3;
    split_bf16(v.x, h0, l0); split_bf16(v.y, h1, l1);
    split_bf16(v.z, h2, l2); split_bf16(v.w, h3, l3);
    *reinterpret_cast<uint2*>(g_Khi + e) = make_uint2(h0 | (h1 << 16), h2 | (h3 << 16));
    *reinterpret_cast<uint2*>(g_Klo + e) = make_uint2(l0 | (l1 << 16), l2 | (l3 << 16));
}

__global__ void prep_keys_kernel(const float* __restrict__ nor_keys,
                                 const float* __restrict__ abn_keys,
                                 const float* __restrict__ cls_mem_w) {
    const int j = blockIdx.x * 8 + (threadIdx.x >> 5);
    const int lane = threadIdx.x & 31;
    const float* key = (j < 512) ? (nor_keys + (size_t)j * DOUT)
                                 : (abn_keys + (size_t)(j - 512) * DOUT);
    const float* w2 = cls_mem_w + DOUT;
    float kv = 0.f, kn = 0.f;
#pragma unroll
    for (int t = 0; t < 4; t++) {
        const int c = (lane + t * 32) * 4;
        float4 k4 = *reinterpret_cast<const float4*>(key + c);
        float4 w4 = *reinterpret_cast<const float4*>(w2 + c);
        kv += k4.x * w4.x + k4.y * w4.y + k4.z * w4.z + k4.w * w4.w;
        kn += k4.x * k4.x + k4.y * k4.y + k4.z * k4.z + k4.w * k4.w;
    }
#pragma unroll
    for (int o = 16; o; o >>= 1) {
        kv += __shfl_xor_sync(0xffffffffu, kv, o);
        kn += __shfl_xor_sync(0xffffffffu, kn, o);
    }
    if (lane == 0) { g_kv[j] = kv; g_kkn[j] = kn; }
}

// ============================================================
// 3-pass bf16 MMA over one 128x128x64 chunk in SW128 SMEM
// 8 warps as 4(M)x2(N): warp tile 32x64.
// ============================================================
__device__ __forceinline__ void mma_chunk_sw(uint32_t st, float acc[2][8][4],
                                             int wm, int wn, int lane)
{
    const int lrow  = lane & 15;
    const int khalf = lane >> 4;
#pragma unroll
    for (int ks = 0; ks < 4; ks++) {
        const uint32_t kb = ks * 32 + khalf * 16;
        uint32_t ah[2][4], al[2][4];
#pragma unroll
        for (int mf = 0; mf < 2; mf++) {
            const uint32_t ro = (uint32_t)((wm + mf * 16 + lrow) * 128) + kb;
            LDMATRIX_X4(ah[mf][0], ah[mf][1], ah[mf][2], ah[mf][3], st + M_AH + SW128(ro));
            LDMATRIX_X4(al[mf][0], al[mf][1], al[mf][2], al[mf][3], st + M_AL + SW128(ro));
        }
        uint32_t bh[4][4], bl[4][4];
#pragma unroll
        for (int nq = 0; nq < 4; nq++) {
            const uint32_t ro = (uint32_t)((wn + nq * 16 + lrow) * 128) + kb;
            LDMATRIX_X4(bh[nq][0], bh[nq][1], bh[nq][2], bh[nq][3], st + M_BH + SW128(ro));
            LDMATRIX_X4(bl[nq][0], bl[nq][1], bl[nq][2], bl[nq][3], st + M_BL + SW128(ro));
        }
#pragma unroll
        for (int mf = 0; mf < 2; mf++)
#pragma unroll
            for (int nq = 0; nq < 4; nq++)
#pragma unroll
                for (int nh = 0; nh < 2; nh++) {
                    float* d = acc[mf][nq * 2 + nh];
                    MMA_BF16(d, ah[mf], bh[nq][nh], bh[nq][nh + 2]);   // AhBh
                    MMA_BF16(d, ah[mf], bl[nq][nh], bl[nq][nh + 2]);   // AhBl
                    MMA_BF16(d, al[mf], bh[nq][nh], bh[nq][nh + 2]);   // AlBh
                }
    }
}

// ============================================================
// Winograd GEMM: M_p = U_p @ V_p^T  (6 points, 2048x512x2048 each)
// grid (4 n-tiles, 16 m-tiles, 6 points)
// ============================================================
__global__ void __launch_bounds__(256, 1) wino_gemm_kernel(
    const __grid_constant__ CUtensorMap mUh,
    const __grid_constant__ CUtensorMap mUl,
    const __grid_constant__ CUtensorMap mVh,
    const __grid_constant__ CUtensorMap mVl)
{
    extern __shared__ char smem[];
    const uint32_t sb = smem_u32(smem);
    const int tid  = threadIdx.x;
    const int wid  = tid >> 5;
    const int lane = tid & 31;
    const int bm = blockIdx.y * 128;
    const int bn = blockIdx.x * 128;
    const int p  = blockIdx.z;
    const int wm = (wid >> 1) * 32;
    const int wn = (wid & 1) * 64;

    float acc[2][8][4];
#pragma unroll
    for (int i = 0; i < 2; i++)
#pragma unroll
        for (int j = 0; j < 8; j++)
#pragma unroll
            for (int c = 0; c < 4; c++) acc[i][j][c] = 0.f;

    if (tid == 0) {
        MBARRIER_INIT(sb + 0, 1);
        MBARRIER_INIT(sb + 8, 1);
        MBARRIER_INIT(sb + 16, 1);
    }
    __syncthreads();

    const int CHUNKS = DIN / 64;   // 32
    auto issue = [&](int i) {
        const int s = i % NSTAGE;
        const uint32_t st = sb + STG_BASE + s * STG_BYTES;
        const uint32_t mb = sb + s * 8;
        const int k0 = i * 64;
        MBARRIER_EXPECT_TX(mb, STG_BYTES);
        TMA_2D(st + M_AH, &mUh, k0, p * GT + bm, mb);
        TMA_2D(st + M_AL, &mUl, k0, p * GT + bm, mb);
        TMA_2D(st + M_BH, &mVh, k0, p * DOUT + bn, mb);
        TMA_2D(st + M_BL, &mVl, k0, p * DOUT + bn, mb);
    };
    if (tid == 0) { issue(0); issue(1); issue(2); }

    for (int i = 0; i < CHUNKS; i++) {
        const int s = i % NSTAGE;
        MBARRIER_WAIT_PARITY(sb + s * 8, (uint32_t)((i / NSTAGE) & 1));
        mma_chunk_sw(sb + STG_BASE + s * STG_BYTES, acc, wm, wn, lane);
        __syncthreads();
        if (tid == 0 && i + NSTAGE < CHUNKS) issue(i + NSTAGE);
    }

#pragma unroll
    for (int mf = 0; mf < 2; mf++) {
        const int row0 = bm + wm + mf * 16 + (lane >> 2);
#pragma unroll
        for (int nf = 0; nf < 8; nf++) {
            const int col = bn + wn + nf * 8 + (lane & 3) * 2;
#pragma unroll
            for (int h = 0; h < 2; h++) {
                const int row = row0 + h * 8;
                *reinterpret_cast<float2*>(
                    g_M + ((size_t)(p * GT) + row) * DOUT + col) =
                    make_float2(acc[mf][nf][2 * h], acc[mf][nf][2 * h + 1]);
            }
        }
    }
}

// ============================================================
// Winograd output transform + bias + relu -> E (fp32 + bf16 hi/lo)
// fused rowstats (p_score, w1dot, qq). One block per tile gt, 512 threads.
// ============================================================
__global__ void __launch_bounds__(512) wino_out_kernel(
    const float* __restrict__ bias,
    const float* __restrict__ cls_w,
    const float* __restrict__ cls_b,
    const float* __restrict__ cls_mem_w,
    float* __restrict__ E,
    float* __restrict__ p_out)
{
    const int gt = blockIdx.x;
    const int o  = threadIdx.x;
    float m[6];
#pragma unroll
    for (int p = 0; p < 6; p++)
        m[p] = g_M[((size_t)(p * GT) + gt) * DOUT + o];

    float y[4];
    y[0] = m[0] + m[1] + m[2] + m[3] + m[4];
    y[1] = m[1] - m[2] + 2.f * (m[3] - m[4]);
    y[2] = m[1] + m[2] + 4.f * (m[3] + m[4]);
    y[3] = m[1] - m[2] + 8.f * (m[3] - m[4]) + m[5];

    const float b  = bias[o];
    const float w0 = cls_w[o];
    const float w1 = cls_mem_w[o];

    __shared__ float red[16][12];
    const int lane = o & 31, wrp = o >> 5;

    float d0[4], d1[4], qq[4];
#pragma unroll
    for (int r = 0; r < 4; r++) {
        const float v = fmaxf(y[r] + b, 0.f);
        const int row = 4 * gt + r;
        E[(size_t)row * DOUT + o] = v;
        uint32_t h, l;
        split_bf16(v, h, l);
        g_Ehi[(size_t)row * DOUT + o] = __ushort_as_bfloat16((unsigned short)h);
        g_Elo[(size_t)row * DOUT + o] = __ushort_as_bfloat16((unsigned short)l);
        d0[r] = v * w0;
        d1[r] = v * w1;
        qq[r] = v * v;
    }
#pragma unroll
    for (int r = 0; r < 4; r++) {
#pragma unroll
        for (int off = 16; off; off >>= 1) {
            d0[r] += __shfl_xor_sync(0xffffffffu, d0[r], off);
            d1[r] += __shfl_xor_sync(0xffffffffu, d1[r], off);
            qq[r] += __shfl_xor_sync(0xffffffffu, qq[r], off);
        }
        if (lane == 0) {
            red[wrp][3 * r + 0] = d0[r];
            red[wrp][3 * r + 1] = d1[r];
            red[wrp][3 * r + 2] = qq[r];
        }
    }
    __syncthreads();
    if (o < 12) {
        float s = 0.f;
#pragma unroll
        for (int w = 0; w < 16; w++) s += red[w][o];
        const int r = o / 3, q = o - 3 * r;
        const int row = 4 * gt + r;
        if (q == 0)      p_out[row]   = 1.f / (1.f + __expf(-(s + cls_b[0])));
        else if (q == 1) g_w1dot[row] = s;
        else             g_qq[row]    = s;
    }
}

// ============================================================
// score GEMM: S = E @ keys^T, tile 128x128, K=512, TMA feed
// ============================================================
__global__ void __launch_bounds__(256, 1) score_mma_kernel(
    const __grid_constant__ CUtensorMap mEh,
    const __grid_constant__ CUtensorMap mEl,
    const __grid_constant__ CUtensorMap mKh,
    const __grid_constant__ CUtensorMap mKl)
{
    extern __shared__ char smem[];
    const uint32_t sb = smem_u32(smem);
    const int tid  = threadIdx.x;
    const int wid  = tid >> 5;
    const int lane = tid & 31;
    const int bm = blockIdx.y * 128;
    const int bn = blockIdx.x * 128;
    const int wm = (wid >> 1) * 32;
    const int wn = (wid & 1) * 64;

    float acc[2][8][4];
#pragma unroll
    for (int i = 0; i < 2; i++)
#pragma unroll
        for (int j = 0; j < 8; j++)
#pragma unroll
            for (int c = 0; c < 4; c++) acc[i][j][c] = 0.f;

    if (tid == 0) {
        MBARRIER_INIT(sb + 0, 1);
        MBARRIER_INIT(sb + 8, 1);
        MBARRIER_INIT(sb + 16, 1);
    }
    __syncthreads();

    const int CHUNKS = DOUT / 64;   // 8
    auto issue = [&](int i) {
        const int s = i % NSTAGE;
        const uint32_t st = sb + STG_BASE + s * STG_BYTES;
        const uint32_t mb = sb + s * 8;
        const int k0 = i * 64;
        MBARRIER_EXPECT_TX(mb, STG_BYTES);
        TMA_2D(st + M_AH, &mEh, k0, bm, mb);
        TMA_2D(st + M_AL, &mEl, k0, bm, mb);
        TMA_2D(st + M_BH, &mKh, k0, bn, mb);
        TMA_2D(st + M_BL, &mKl, k0, bn, mb);
    };
    if (tid == 0) { issue(0); issue(1); issue(2); }

    for (int i = 0; i < CHUNKS; i++) {
        const int s = i % NSTAGE;
        MBARRIER_WAIT_PARITY(sb + s * 8, (uint32_t)((i / NSTAGE) & 1));
        mma_chunk_sw(sb + STG_BASE + s * STG_BYTES, acc, wm, wn, lane);
        __syncthreads();
        if (tid == 0 && i + NSTAGE < CHUNKS) issue(i + NSTAGE);
    }

#pragma unroll
    for (int mf = 0; mf < 2; mf++) {
        const int row0 = bm + wm + mf * 16 + (lane >> 2);
#pragma unroll
        for (int nf = 0; nf < 8; nf++) {
            const int col = bn + wn + nf * 8 + (lane & 3) * 2;
#pragma unroll
            for (int h = 0; h < 2; h++) {
                const int row = row0 + h * 8;
                *reinterpret_cast<float2*>(g_S + (size_t)row * NKEYS + col) =
                    make_float2(acc[mf][nf][2 * h], acc[mf][nf][2 * h + 1]);
            }
        }
    }
}

// ============================================================
// softmax / argmax reduction over S rows
// ============================================================
__global__ void softmax_reduce_kernel(const float* __restrict__ cls_mem_b,
                                      float* __restrict__ up_out,
                                      float* __restrict__ nor_out,
                                      float* __restrict__ abn_out)
{
    const int row  = blockIdx.x * 8 + (threadIdx.x >> 5);
    const int lane = threadIdx.x & 31;
    const float* Sr = g_S + (size_t)row * NKEYS;

    float s[32];
    float m = -INFINITY;
    float bv0 = -INFINITY, bv1 = -INFINITY;
    int bi0 = 0, bi1 = 0;
#pragma unroll
    for (int t = 0; t < 32; t++) {
        const int j = t * 32 + lane;
        const float v = Sr[j];
        s[t] = v;
        m = fmaxf(m, v);
        if (t < 16) { if (v > bv0) { bv0 = v; bi0 = j; } }
        else        { if (v > bv1) { bv1 = v; bi1 = j; } }
    }
#pragma unroll
    for (int o = 16; o; o >>= 1) m = fmaxf(m, __shfl_xor_sync(0xffffffffu, m, o));

    float l = 0.f, dsum = 0.f;
#pragma unroll
    for (int t = 0; t < 32; t++) {
        const int j = t * 32 + lane;
        const float e = __expf(s[t] - m);
        l += e;
        dsum += e * g_kv[j];
    }
#pragma unroll
    for (int o = 16; o; o >>= 1) {
        l    += __shfl_xor_sync(0xffffffffu, l, o);
        dsum += __shfl_xor_sync(0xffffffffu, dsum, o);
    }
#pragma unroll
    for (int o = 16; o; o >>= 1) {
        const float o0 = __shfl_xor_sync(0xffffffffu, bv0, o);
        const int   i0 = __shfl_xor_sync(0xffffffffu, bi0, o);
        if (o0 > bv0 || (o0 == bv0 && i0 < bi0)) { bv0 = o0; bi0 = i0; }
        const float o1 = __shfl_xor_sync(0xffffffffu, bv1, o);
        const int   i1 = __shfl_xor_sync(0xffffffffu, bi1, o);
        if (o1 > bv1 || (o1 == bv1 && i1 < bi1)) { bv1 = o1; bi1 = i1; }
    }
    if (lane == 0) {
        const float x = g_w1dot[row] + dsum / l + cls_mem_b[0];
        up_out[row] = 1.f / (1.f + __expf(-x));
        const float qq = g_qq[row];
        nor_out[row] = (qq - 2.f * bv0 + g_kkn[bi0]) * (1.f / 512.f);
        abn_out[row] = (qq - 2.f * bv1 + g_kkn[bi1]) * (1.f / 512.f);
    }
}

// ============================================================
// host: tensormap construction (driver entry point via cudart; no -lcuda)
// ============================================================
typedef CUresult (*PFN_tmEnc)(CUtensorMap*, CUtensorMapDataType, cuuint32_t, void*,
                              const cuuint64_t*, const cuuint64_t*, const cuuint32_t*,
                              const cuuint32_t*, CUtensorMapInterleave, CUtensorMapSwizzle,
                              CUtensorMapL2promotion, CUtensorMapFloatOOBfill);

static void enc2d(PFN_tmEnc f, CUtensorMap* m, void* addr,
                  unsigned long long d0, unsigned long long d1,
                  unsigned long long stride_bytes)
{
    cuuint64_t dims[2]    = {(cuuint64_t)d0, (cuuint64_t)d1};
    cuuint64_t strides[1] = {(cuuint64_t)stride_bytes};
    cuuint32_t box[2]     = {64u, 128u};
    cuuint32_t es[2]      = {1u, 1u};
    f(m, CU_TENSOR_MAP_DATA_TYPE_BFLOAT16, 2, addr, dims, strides, box, es,
      CU_TENSOR_MAP_INTERLEAVE_NONE, CU_TENSOR_MAP_SWIZZLE_128B,
      CU_TENSOR_MAP_L2_PROMOTION_L2_128B, CU_TENSOR_MAP_FLOAT_OOB_FILL_NONE);
}

extern "C" void kernel_launch(void* const* d_in, const int* in_sizes, int n_in,
                              void* d_out, int out_size)
{
    const float* ref_nor   = (const float*)d_in[0];
    // d_in[1] = ref_abn : dead (only feeds the discarded p_score[B:])
    const float* nor_keys  = (const float*)d_in[2];
    const float* abn_keys  = (const float*)d_in[3];
    const float* conv_w    = (const float*)d_in[4];
    const float* conv_b    = (const float*)d_in[5];
    const float* cls_w     = (const float*)d_in[6];
    const float* cls_b     = (const float*)d_in[7];
    const float* cls_mem_w = (const float*)d_in[8];
    const float* cls_mem_b = (const float*)d_in[9];

    float* out      = (float*)d_out;
    float* p_score  = out;
    float* up_score = out + ROWS;
    float* nor_loss = out + 2 * ROWS;
    float* abn_loss = out + 3 * ROWS;
    float* E        = out + 4 * ROWS;

    PFN_tmEnc enc = nullptr;
    cudaDriverEntryPointQueryResult qr;
    cudaGetDriverEntryPoint("cuTensorMapEncodeTiled", (void**)&enc,
                            cudaEnableDefault, &qr);
    void *pUh, *pUl, *pVh, *pVl, *pEh, *pEl, *pKh, *pKl;
    cudaGetSymbolAddress(&pUh, g_Uhi); cudaGetSymbolAddress(&pUl, g_Ulo);
    cudaGetSymbolAddress(&pVh, g_Vhi); cudaGetSymbolAddress(&pVl, g_Vlo);
    cudaGetSymbolAddress(&pEh, g_Ehi); cudaGetSymbolAddress(&pEl, g_Elo);
    cudaGetSymbolAddress(&pKh, g_Khi); cudaGetSymbolAddress(&pKl, g_Klo);

    CUtensorMap mUh, mUl, mVh, mVl, mEh, mEl, mKh, mKl;
    enc2d(enc, &mUh, pUh, DIN,  NPTS * GT,   (unsigned long long)DIN  * 2);
    enc2d(enc, &mUl, pUl, DIN,  NPTS * GT,   (unsigned long long)DIN  * 2);
    enc2d(enc, &mVh, pVh, DIN,  NPTS * DOUT, (unsigned long long)DIN  * 2);
    enc2d(enc, &mVl, pVl, DIN,  NPTS * DOUT, (unsigned long long)DIN  * 2);
    enc2d(enc, &mEh, pEh, DOUT, ROWS,        (unsigned long long)DOUT * 2);
    enc2d(enc, &mEl, pEl, DOUT, ROWS,        (unsigned long long)DOUT * 2);
    enc2d(enc, &mKh, pKh, DOUT, NKEYS,       (unsigned long long)DOUT * 2);
    enc2d(enc, &mKl, pKl, DOUT, NKEYS,       (unsigned long long)DOUT * 2);

    cudaFuncSetAttribute(wino_gemm_kernel,  cudaFuncAttributeMaxDynamicSharedMemorySize, SMEM_BYTES);
    cudaFuncSetAttribute(score_mma_kernel, cudaFuncAttributeMaxDynamicSharedMemorySize, SMEM_BYTES);

    wino_input_kernel<<<GT, 256>>>(ref_nor);
    wino_weight_kernel<<<(DOUT * DIN) / 256, 256>>>(conv_w);
    convert_keys_kernel<<<512, 256>>>(nor_keys, abn_keys);
    prep_keys_kernel<<<128, 256>>>(nor_keys, abn_keys, cls_mem_w);

    wino_gemm_kernel<<<dim3(4, 16, 6), 256, SMEM_BYTES>>>(mUh, mUl, mVh, mVl);
    wino_out_kernel<<<GT, 512>>>(conv_b, cls_w, cls_b, cls_mem_w, E, p_score);
    score_mma_kernel<<<dim3(8, 64), 256, SMEM_BYTES>>>(mEh, mEl, mKh, mKl);
    softmax_reduce_kernel<<<1024, 256>>>(cls_mem_b, up_score, nor_loss, abn_loss);
}

// round 6
// speedup vs baseline: 4.6300x; 1.0262x over previous
#include <cuda.h>
#include <cuda_runtime.h>
#include <cuda_fp16.h>
#include <math.h>
#include <stdint.h>

// Problem constants (B=32, N=256, D=2048, d=512, M=512)
#define ROWS  8192      // B*N
#define DIN   2048      // D
#define DOUT  512       // d
#define NKEYS 1024      // 2*M
#define NSEQ  256       // N
#define GT    2048      // B*64 winograd tiles
#define NPTS  6         // winograd F(4,3) points

// ---------------- scratch (device globals; no allocation allowed) ----------------
__device__ __align__(1024) __half g_Uhi[NPTS * GT * DIN];
__device__ __align__(1024) __half g_Ulo[NPTS * GT * DIN];
__device__ __align__(1024) __half g_Vhi[NPTS * DOUT * DIN];
__device__ __align__(1024) __half g_Vlo[NPTS * DOUT * DIN];
__device__ float g_M[(size_t)NPTS * GT * DOUT];
__device__ __align__(1024) __half g_Ehi[ROWS * DOUT];
__device__ __align__(1024) __half g_Elo[ROWS * DOUT];
__device__ __align__(1024) __half g_Khi[NKEYS * DOUT];
__device__ __align__(1024) __half g_Klo[NKEYS * DOUT];
__device__ float g_S[(size_t)ROWS * NKEYS];
__device__ float g_kv[NKEYS];
__device__ float g_kkn[NKEYS];
__device__ float g_w1dot[ROWS];
__device__ float g_qq[ROWS];

// ---------------- device helpers ----------------
__device__ __forceinline__ uint32_t smem_u32(const void* p) {
    uint32_t a;
    asm("{ .reg .u64 t; cvta.to.shared.u64 t, %1; cvt.u32.u64 %0, t; }" : "=r"(a) : "l"(p));
    return a;
}

#define MBARRIER_INIT(addr, cnt) \
    asm volatile("mbarrier.init.shared.b64 [%0], %1;" :: "r"((uint32_t)(addr)), "r"((uint32_t)(cnt)) : "memory")
#define MBARRIER_EXPECT_TX(addr, bytes) \
    asm volatile("mbarrier.arrive.expect_tx.shared.b64 _, [%0], %1;" :: "r"((uint32_t)(addr)), "r"((uint32_t)(bytes)) : "memory")
#define MBARRIER_WAIT_PARITY(addr, parity) do {                                        \
    uint32_t _m = (uint32_t)(addr); uint32_t _p = (uint32_t)(parity); uint32_t _d;     \
    asm volatile("{\n\t.reg .pred p;\n\t"                                              \
        "mbarrier.try_wait.parity.acquire.cta.shared::cta.b64 p, [%1], %2;\n\t"        \
        "selp.b32 %0, 1, 0, p;\n\t}"                                                   \
        : "=r"(_d) : "r"(_m), "r"(_p) : "memory");                                     \
    if (!_d) {                                                                         \
        asm volatile("{\n\t.reg .pred P1;\n\t"                                         \
            "WL_%=:\n\t"                                                               \
            "mbarrier.try_wait.parity.acquire.cta.shared::cta.b64 P1, [%0], %1, 0x989680;\n\t" \
            "@P1 bra.uni WD_%=;\n\t"                                                   \
            "bra.uni WL_%=;\n\t"                                                       \
            "WD_%=:\n\t}"                                                              \
            :: "r"(_m), "r"(_p) : "memory");                                           \
    }                                                                                  \
} while (0)

#define TMA_2D(smaddr, map, x, y, mbar) \
    asm volatile("cp.async.bulk.tensor.2d.shared::cta.global.tile.mbarrier::complete_tx::bytes " \
                 "[%0], [%1, {%2, %3}], [%4];" \
                 :: "r"((uint32_t)(smaddr)), "l"(map), "r"((int)(x)), "r"((int)(y)), \
                    "r"((uint32_t)(mbar)) : "memory")

#define LDMATRIX_X4(r0, r1, r2, r3, addr) \
    asm volatile("ldmatrix.sync.aligned.m8n8.x4.shared.b16 {%0,%1,%2,%3}, [%4];" \
                 : "=r"(r0), "=r"(r1), "=r"(r2), "=r"(r3) : "r"(addr))

// main pass: fp16 x fp16 -> fp32 accum
#define MMA_F16_F32(d, a, b0v, b1v) \
    asm volatile("mma.sync.aligned.m16n8k16.row.col.f32.f16.f16.f32 " \
                 "{%0,%1,%2,%3}, {%4,%5,%6,%7}, {%8,%9}, {%0,%1,%2,%3};" \
                 : "+f"((d)[0]), "+f"((d)[1]), "+f"((d)[2]), "+f"((d)[3]) \
                 : "r"((a)[0]), "r"((a)[1]), "r"((a)[2]), "r"((a)[3]), \
                   "r"(b0v), "r"(b1v))

// correction pass: fp16 x fp16 -> fp16 accum (packed f16x2 x2)
#define MMA_F16_F16(d, a, b0v, b1v) \
    asm volatile("mma.sync.aligned.m16n8k16.row.col.f16.f16.f16.f16 " \
                 "{%0,%1}, {%2,%3,%4,%5}, {%6,%7}, {%0,%1};" \
                 : "+r"((d)[0]), "+r"((d)[1]) \
                 : "r"((a)[0]), "r"((a)[1]), "r"((a)[2]), "r"((a)[3]), \
                   "r"(b0v), "r"(b1v))

__device__ __forceinline__ void split_f16(float x, uint32_t& h, uint32_t& l) {
    __half hb = __float2half_rn(x);
    float hf = __half2float(hb);
    __half lb = __float2half_rn(x - hf);
    h = (uint32_t)__half_as_ushort(hb);
    l = (uint32_t)__half_as_ushort(lb);
}

#define SW128(b) ((b) ^ (((b) >> 3) & 0x70))

// SMEM: barriers [0,24), stages at 1024 + s*65536. Matrices: AH, AL, BH, BL (16KB each).
#define STG_BASE   1024
#define STG_BYTES  65536
#define M_AH 0
#define M_AL 16384
#define M_BH 32768
#define M_BL 49152
#define NSTAGE 3
#define SMEM_BYTES (STG_BASE + NSTAGE * STG_BYTES)   // 197632

// ============================================================
// Winograd F(4,3) input transform: X -> U_p (fp16 hi/lo), p=0..5
// ============================================================
__global__ void wino_input_kernel(const float* __restrict__ X)
{
    const int gt = blockIdx.x;          // b*64 + t
    const int b = gt >> 6, t = gt & 63;
    const int n0 = 4 * t - 1;
#pragma unroll
    for (int cc = 0; cc < 8; cc++) {
        const int c = threadIdx.x + cc * 256;
        float d[6];
#pragma unroll
        for (int i = 0; i < 6; i++) {
            const int n = n0 + i;
            d[i] = (n >= 0 && n < NSEQ) ? X[((size_t)b * NSEQ + n) * DIN + c] : 0.f;
        }
        float u[6];
        u[0] =  4.f * d[0] - 5.f * d[2] + d[4];
        u[1] = -4.f * (d[1] + d[2]) + d[3] + d[4];
        u[2] =  4.f * d[1] - 4.f * d[2] - d[3] + d[4];
        u[3] = -2.f * d[1] - d[2] + 2.f * d[3] + d[4];
        u[4] =  2.f * d[1] - d[2] - 2.f * d[3] + d[4];
        u[5] =  4.f * d[1] - 5.f * d[3] + d[5];
#pragma unroll
        for (int p = 0; p < 6; p++) {
            uint32_t h, l;
            split_f16(u[p], h, l);
            const size_t off = ((size_t)(p * GT + gt)) * DIN + c;
            g_Uhi[off] = __ushort_as_half((unsigned short)h);
            g_Ulo[off] = __ushort_as_half((unsigned short)l);
        }
    }
}

// ============================================================
// Winograd weight transform: conv_w (o, c, 3) -> V_p[o][c]
// ============================================================
__global__ void wino_weight_kernel(const float* __restrict__ conv_w)
{
    const int idx = blockIdx.x * 256 + threadIdx.x;   // o*2048 + c
    const float w0 = conv_w[3 * (size_t)idx + 0];
    const float w1 = conv_w[3 * (size_t)idx + 1];
    const float w2 = conv_w[3 * (size_t)idx + 2];
    float v[6];
    v[0] =  0.25f * w0;
    v[1] = -(w0 + w1 + w2) * (1.f / 6.f);
    v[2] = (-w0 + w1 - w2) * (1.f / 6.f);
    v[3] =  w0 * (1.f / 24.f) + w1 * (1.f / 12.f) + w2 * (1.f / 6.f);
    v[4] =  w0 * (1.f / 24.f) - w1 * (1.f / 12.f) + w2 * (1.f / 6.f);
    v[5] =  w2;
    const int o = idx >> 11, c = idx & 2047;
#pragma unroll
    for (int p = 0; p < 6; p++) {
        uint32_t h, l;
        split_f16(v[p], h, l);
        const size_t off = ((size_t)(p * DOUT + o)) * DIN + c;
        g_Vhi[off] = __ushort_as_half((unsigned short)h);
        g_Vlo[off] = __ushort_as_half((unsigned short)l);
    }
}

// ============================================================
// keys -> fp16 hi/lo (concat nor|abn)
// ============================================================
__global__ void convert_keys_kernel(const float* __restrict__ nor_keys,
                                    const float* __restrict__ abn_keys) {
    size_t e = ((size_t)blockIdx.x * 256 + threadIdx.x) * 4;
    int j = (int)(e >> 9);
    int col = (int)(e & 511);
    const float* src = (j < 512) ? (nor_keys + (size_t)j * DOUT + col)
                                 : (abn_keys + (size_t)(j - 512) * DOUT + col);
    float4 v = *reinterpret_cast<const float4*>(src);
    uint32_t h0, l0, h1, l1, h2, l2, h3, l3;
    split_f16(v.x, h0, l0); split_f16(v.y, h1, l1);
    split_f16(v.z, h2, l2); split_f16(v.w, h3, l3);
    *reinterpret_cast<uint2*>(g_Khi + e) = make_uint2(h0 | (h1 << 16), h2 | (h3 << 16));
    *reinterpret_cast<uint2*>(g_Klo + e) = make_uint2(l0 | (l1 << 16), l2 | (l3 << 16));
}

__global__ void prep_keys_kernel(const float* __restrict__ nor_keys,
                                 const float* __restrict__ abn_keys,
                                 const float* __restrict__ cls_mem_w) {
    const int j = blockIdx.x * 8 + (threadIdx.x >> 5);
    const int lane = threadIdx.x & 31;
    const float* key = (j < 512) ? (nor_keys + (size_t)j * DOUT)
                                 : (abn_keys + (size_t)(j - 512) * DOUT);
    const float* w2 = cls_mem_w + DOUT;
    float kv = 0.f, kn = 0.f;
#pragma unroll
    for (int t = 0; t < 4; t++) {
        const int c = (lane + t * 32) * 4;
        float4 k4 = *reinterpret_cast<const float4*>(key + c);
        float4 w4 = *reinterpret_cast<const float4*>(w2 + c);
        kv += k4.x * w4.x + k4.y * w4.y + k4.z * w4.z + k4.w * w4.w;
        kn += k4.x * k4.x + k4.y * k4.y + k4.z * k4.z + k4.w * k4.w;
    }
#pragma unroll
    for (int o = 16; o; o >>= 1) {
        kv += __shfl_xor_sync(0xffffffffu, kv, o);
        kn += __shfl_xor_sync(0xffffffffu, kn, o);
    }
    if (lane == 0) { g_kv[j] = kv; g_kkn[j] = kn; }
}

// ============================================================
// 2.5-pass fp16 MMA over one 128x128x64 chunk in SW128 SMEM.
// Main AhBh -> f32 accum; corrections AhBl + AlBh -> shared f16 accum.
// 8 warps as 4(M)x2(N): warp tile 32x64.
// ============================================================
__device__ __forceinline__ void mma_chunk_sw(uint32_t st,
                                             float accf[2][8][4],
                                             uint32_t acch[2][8][2],
                                             int wm, int wn, int lane)
{
    const int lrow  = lane & 15;
    const int khalf = lane >> 4;
#pragma unroll
    for (int ks = 0; ks < 4; ks++) {
        const uint32_t kb = ks * 32 + khalf * 16;
        uint32_t ah[2][4], al[2][4];
#pragma unroll
        for (int mf = 0; mf < 2; mf++) {
            const uint32_t ro = (uint32_t)((wm + mf * 16 + lrow) * 128) + kb;
            LDMATRIX_X4(ah[mf][0], ah[mf][1], ah[mf][2], ah[mf][3], st + M_AH + SW128(ro));
            LDMATRIX_X4(al[mf][0], al[mf][1], al[mf][2], al[mf][3], st + M_AL + SW128(ro));
        }
        uint32_t bh[4][4], bl[4][4];
#pragma unroll
        for (int nq = 0; nq < 4; nq++) {
            const uint32_t ro = (uint32_t)((wn + nq * 16 + lrow) * 128) + kb;
            LDMATRIX_X4(bh[nq][0], bh[nq][1], bh[nq][2], bh[nq][3], st + M_BH + SW128(ro));
            LDMATRIX_X4(bl[nq][0], bl[nq][1], bl[nq][2], bl[nq][3], st + M_BL + SW128(ro));
        }
#pragma unroll
        for (int mf = 0; mf < 2; mf++)
#pragma unroll
            for (int nq = 0; nq < 4; nq++)
#pragma unroll
                for (int nh = 0; nh < 2; nh++) {
                    MMA_F16_F32(accf[mf][nq * 2 + nh], ah[mf], bh[nq][nh], bh[nq][nh + 2]);
                    MMA_F16_F16(acch[mf][nq * 2 + nh], ah[mf], bl[nq][nh], bl[nq][nh + 2]);
                    MMA_F16_F16(acch[mf][nq * 2 + nh], al[mf], bh[nq][nh], bh[nq][nh + 2]);
                }
    }
}

__device__ __forceinline__ float frag_val(const float accf[4], const uint32_t acch[2], int idx) {
    // idx 0..3: f32 frag element; corrections packed as half2 per register
    const __half2 c = *reinterpret_cast<const __half2*>(&acch[idx >> 1]);
    const float corr = (idx & 1) ? __high2float(c) : __low2float(c);
    return accf[idx] + corr;
}

// ============================================================
// Winograd GEMM: M_p = U_p @ V_p^T  (6 points, 2048x512x2048 each)
// ============================================================
__global__ void __launch_bounds__(256, 1) wino_gemm_kernel(
    const __grid_constant__ CUtensorMap mUh,
    const __grid_constant__ CUtensorMap mUl,
    const __grid_constant__ CUtensorMap mVh,
    const __grid_constant__ CUtensorMap mVl)
{
    extern __shared__ char smem[];
    const uint32_t sb = smem_u32(smem);
    const int tid  = threadIdx.x;
    const int wid  = tid >> 5;
    const int lane = tid & 31;
    const int bm = blockIdx.y * 128;
    const int bn = blockIdx.x * 128;
    const int p  = blockIdx.z;
    const int wm = (wid >> 1) * 32;
    const int wn = (wid & 1) * 64;

    float    accf[2][8][4];
    uint32_t acch[2][8][2];
#pragma unroll
    for (int i = 0; i < 2; i++)
#pragma unroll
        for (int j = 0; j < 8; j++) {
#pragma unroll
            for (int c = 0; c < 4; c++) accf[i][j][c] = 0.f;
            acch[i][j][0] = 0u; acch[i][j][1] = 0u;
        }

    if (tid == 0) {
        MBARRIER_INIT(sb + 0, 1);
        MBARRIER_INIT(sb + 8, 1);
        MBARRIER_INIT(sb + 16, 1);
    }
    __syncthreads();

    const int CHUNKS = DIN / 64;   // 32
    auto issue = [&](int i) {
        const int s = i % NSTAGE;
        const uint32_t st = sb + STG_BASE + s * STG_BYTES;
        const uint32_t mb = sb + s * 8;
        const int k0 = i * 64;
        MBARRIER_EXPECT_TX(mb, STG_BYTES);
        TMA_2D(st + M_AH, &mUh, k0, p * GT + bm, mb);
        TMA_2D(st + M_AL, &mUl, k0, p * GT + bm, mb);
        TMA_2D(st + M_BH, &mVh, k0, p * DOUT + bn, mb);
        TMA_2D(st + M_BL, &mVl, k0, p * DOUT + bn, mb);
    };
    if (tid == 0) { issue(0); issue(1); issue(2); }

    for (int i = 0; i < CHUNKS; i++) {
        const int s = i % NSTAGE;
        MBARRIER_WAIT_PARITY(sb + s * 8, (uint32_t)((i / NSTAGE) & 1));
        mma_chunk_sw(sb + STG_BASE + s * STG_BYTES, accf, acch, wm, wn, lane);
        __syncthreads();
        if (tid == 0 && i + NSTAGE < CHUNKS) issue(i + NSTAGE);
    }

#pragma unroll
    for (int mf = 0; mf < 2; mf++) {
        const int row0 = bm + wm + mf * 16 + (lane >> 2);
#pragma unroll
        for (int nf = 0; nf < 8; nf++) {
            const int col = bn + wn + nf * 8 + (lane & 3) * 2;
#pragma unroll
            for (int h = 0; h < 2; h++) {
                const int row = row0 + h * 8;
                *reinterpret_cast<float2*>(
                    g_M + ((size_t)(p * GT) + row) * DOUT + col) =
                    make_float2(frag_val(accf[mf][nf], acch[mf][nf], 2 * h),
                                frag_val(accf[mf][nf], acch[mf][nf], 2 * h + 1));
            }
        }
    }
}

// ============================================================
// Winograd output transform + bias + relu -> E (fp32 + fp16 hi/lo)
// fused rowstats. One block per tile gt, 512 threads.
// ============================================================
__global__ void __launch_bounds__(512) wino_out_kernel(
    const float* __restrict__ bias,
    const float* __restrict__ cls_w,
    const float* __restrict__ cls_b,
    const float* __restrict__ cls_mem_w,
    float* __restrict__ E,
    float* __restrict__ p_out)
{
    const int gt = blockIdx.x;
    const int o  = threadIdx.x;
    float m[6];
#pragma unroll
    for (int p = 0; p < 6; p++)
        m[p] = g_M[((size_t)(p * GT) + gt) * DOUT + o];

    float y[4];
    y[0] = m[0] + m[1] + m[2] + m[3] + m[4];
    y[1] = m[1] - m[2] + 2.f * (m[3] - m[4]);
    y[2] = m[1] + m[2] + 4.f * (m[3] + m[4]);
    y[3] = m[1] - m[2] + 8.f * (m[3] - m[4]) + m[5];

    const float b  = bias[o];
    const float w0 = cls_w[o];
    const float w1 = cls_mem_w[o];

    __shared__ float red[16][12];
    const int lane = o & 31, wrp = o >> 5;

    float d0[4], d1[4], qq[4];
#pragma unroll
    for (int r = 0; r < 4; r++) {
        const float v = fmaxf(y[r] + b, 0.f);
        const int row = 4 * gt + r;
        E[(size_t)row * DOUT + o] = v;
        uint32_t h, l;
        split_f16(v, h, l);
        g_Ehi[(size_t)row * DOUT + o] = __ushort_as_half((unsigned short)h);
        g_Elo[(size_t)row * DOUT + o] = __ushort_as_half((unsigned short)l);
        d0[r] = v * w0;
        d1[r] = v * w1;
        qq[r] = v * v;
    }
#pragma unroll
    for (int r = 0; r < 4; r++) {
#pragma unroll
        for (int off = 16; off; off >>= 1) {
            d0[r] += __shfl_xor_sync(0xffffffffu, d0[r], off);
            d1[r] += __shfl_xor_sync(0xffffffffu, d1[r], off);
            qq[r] += __shfl_xor_sync(0xffffffffu, qq[r], off);
        }
        if (lane == 0) {
            red[wrp][3 * r + 0] = d0[r];
            red[wrp][3 * r + 1] = d1[r];
            red[wrp][3 * r + 2] = qq[r];
        }
    }
    __syncthreads();
    if (o < 12) {
        float s = 0.f;
#pragma unroll
        for (int w = 0; w < 16; w++) s += red[w][o];
        const int r = o / 3, q = o - 3 * r;
        const int row = 4 * gt + r;
        if (q == 0)      p_out[row]   = 1.f / (1.f + __expf(-(s + cls_b[0])));
        else if (q == 1) g_w1dot[row] = s;
        else             g_qq[row]    = s;
    }
}

// ============================================================
// score GEMM: S = E @ keys^T, tile 128x128, K=512, TMA feed
// ============================================================
__global__ void __launch_bounds__(256, 1) score_mma_kernel(
    const __grid_constant__ CUtensorMap mEh,
    const __grid_constant__ CUtensorMap mEl,
    const __grid_constant__ CUtensorMap mKh,
    const __grid_constant__ CUtensorMap mKl)
{
    extern __shared__ char smem[];
    const uint32_t sb = smem_u32(smem);
    const int tid  = threadIdx.x;
    const int wid  = tid >> 5;
    const int lane = tid & 31;
    const int bm = blockIdx.y * 128;
    const int bn = blockIdx.x * 128;
    const int wm = (wid >> 1) * 32;
    const int wn = (wid & 1) * 64;

    float    accf[2][8][4];
    uint32_t acch[2][8][2];
#pragma unroll
    for (int i = 0; i < 2; i++)
#pragma unroll
        for (int j = 0; j < 8; j++) {
#pragma unroll
            for (int c = 0; c < 4; c++) accf[i][j][c] = 0.f;
            acch[i][j][0] = 0u; acch[i][j][1] = 0u;
        }

    if (tid == 0) {
        MBARRIER_INIT(sb + 0, 1);
        MBARRIER_INIT(sb + 8, 1);
        MBARRIER_INIT(sb + 16, 1);
    }
    __syncthreads();

    const int CHUNKS = DOUT / 64;   // 8
    auto issue = [&](int i) {
        const int s = i % NSTAGE;
        const uint32_t st = sb + STG_BASE + s * STG_BYTES;
        const uint32_t mb = sb + s * 8;
        const int k0 = i * 64;
        MBARRIER_EXPECT_TX(mb, STG_BYTES);
        TMA_2D(st + M_AH, &mEh, k0, bm, mb);
        TMA_2D(st + M_AL, &mEl, k0, bm, mb);
        TMA_2D(st + M_BH, &mKh, k0, bn, mb);
        TMA_2D(st + M_BL, &mKl, k0, bn, mb);
    };
    if (tid == 0) { issue(0); issue(1); issue(2); }

    for (int i = 0; i < CHUNKS; i++) {
        const int s = i % NSTAGE;
        MBARRIER_WAIT_PARITY(sb + s * 8, (uint32_t)((i / NSTAGE) & 1));
        mma_chunk_sw(sb + STG_BASE + s * STG_BYTES, accf, acch, wm, wn, lane);
        __syncthreads();
        if (tid == 0 && i + NSTAGE < CHUNKS) issue(i + NSTAGE);
    }

#pragma unroll
    for (int mf = 0; mf < 2; mf++) {
        const int row0 = bm + wm + mf * 16 + (lane >> 2);
#pragma unroll
        for (int nf = 0; nf < 8; nf++) {
            const int col = bn + wn + nf * 8 + (lane & 3) * 2;
#pragma unroll
            for (int h = 0; h < 2; h++) {
                const int row = row0 + h * 8;
                *reinterpret_cast<float2*>(g_S + (size_t)row * NKEYS + col) =
                    make_float2(frag_val(accf[mf][nf], acch[mf][nf], 2 * h),
                                frag_val(accf[mf][nf], acch[mf][nf], 2 * h + 1));
            }
        }
    }
}

// ============================================================
// softmax / argmax reduction over S rows
// ============================================================
__global__ void softmax_reduce_kernel(const float* __restrict__ cls_mem_b,
                                      float* __restrict__ up_out,
                                      float* __restrict__ nor_out,
                                      float* __restrict__ abn_out)
{
    const int row  = blockIdx.x * 8 + (threadIdx.x >> 5);
    const int lane = threadIdx.x & 31;
    const float* Sr = g_S + (size_t)row * NKEYS;

    float s[32];
    float m = -INFINITY;
    float bv0 = -INFINITY, bv1 = -INFINITY;
    int bi0 = 0, bi1 = 0;
#pragma unroll
    for (int t = 0; t < 32; t++) {
        const int j = t * 32 + lane;
        const float v = Sr[j];
        s[t] = v;
        m = fmaxf(m, v);
        if (t < 16) { if (v > bv0) { bv0 = v; bi0 = j; } }
        else        { if (v > bv1) { bv1 = v; bi1 = j; } }
    }
#pragma unroll
    for (int o = 16; o; o >>= 1) m = fmaxf(m, __shfl_xor_sync(0xffffffffu, m, o));

    float l = 0.f, dsum = 0.f;
#pragma unroll
    for (int t = 0; t < 32; t++) {
        const int j = t * 32 + lane;
        const float e = __expf(s[t] - m);
        l += e;
        dsum += e * g_kv[j];
    }
#pragma unroll
    for (int o = 16; o; o >>= 1) {
        l    += __shfl_xor_sync(0xffffffffu, l, o);
        dsum += __shfl_xor_sync(0xffffffffu, dsum, o);
    }
#pragma unroll
    for (int o = 16; o; o >>= 1) {
        const float o0 = __shfl_xor_sync(0xffffffffu, bv0, o);
        const int   i0 = __shfl_xor_sync(0xffffffffu, bi0, o);
        if (o0 > bv0 || (o0 == bv0 && i0 < bi0)) { bv0 = o0; bi0 = i0; }
        const float o1 = __shfl_xor_sync(0xffffffffu, bv1, o);
        const int   i1 = __shfl_xor_sync(0xffffffffu, bi1, o);
        if (o1 > bv1 || (o1 == bv1 && i1 < bi1)) { bv1 = o1; bi1 = i1; }
    }
    if (lane == 0) {
        const float x = g_w1dot[row] + dsum / l + cls_mem_b[0];
        up_out[row] = 1.f / (1.f + __expf(-x));
        const float qq = g_qq[row];
        nor_out[row] = (qq - 2.f * bv0 + g_kkn[bi0]) * (1.f / 512.f);
        abn_out[row] = (qq - 2.f * bv1 + g_kkn[bi1]) * (1.f / 512.f);
    }
}

// ============================================================
// host: tensormap construction (driver entry point via cudart; no -lcuda)
// ============================================================
typedef CUresult (*PFN_tmEnc)(CUtensorMap*, CUtensorMapDataType, cuuint32_t, void*,
                              const cuuint64_t*, const cuuint64_t*, const cuuint32_t*,
                              const cuuint32_t*, CUtensorMapInterleave, CUtensorMapSwizzle,
                              CUtensorMapL2promotion, CUtensorMapFloatOOBfill);

static void enc2d(PFN_tmEnc f, CUtensorMap* m, void* addr,
                  unsigned long long d0, unsigned long long d1,
                  unsigned long long stride_bytes)
{
    cuuint64_t dims[2]    = {(cuuint64_t)d0, (cuuint64_t)d1};
    cuuint64_t strides[1] = {(cuuint64_t)stride_bytes};
    cuuint32_t box[2]     = {64u, 128u};
    cuuint32_t es[2]      = {1u, 1u};
    f(m, CU_TENSOR_MAP_DATA_TYPE_FLOAT16, 2, addr, dims, strides, box, es,
      CU_TENSOR_MAP_INTERLEAVE_NONE, CU_TENSOR_MAP_SWIZZLE_128B,
      CU_TENSOR_MAP_L2_PROMOTION_L2_128B, CU_TENSOR_MAP_FLOAT_OOB_FILL_NONE);
}

extern "C" void kernel_launch(void* const* d_in, const int* in_sizes, int n_in,
                              void* d_out, int out_size)
{
    const float* ref_nor   = (const float*)d_in[0];
    // d_in[1] = ref_abn : dead (only feeds the discarded p_score[B:])
    const float* nor_keys  = (const float*)d_in[2];
    const float* abn_keys  = (const float*)d_in[3];
    const float* conv_w    = (const float*)d_in[4];
    const float* conv_b    = (const float*)d_in[5];
    const float* cls_w     = (const float*)d_in[6];
    const float* cls_b     = (const float*)d_in[7];
    const float* cls_mem_w = (const float*)d_in[8];
    const float* cls_mem_b = (const float*)d_in[9];

    float* out      = (float*)d_out;
    float* p_score  = out;
    float* up_score = out + ROWS;
    float* nor_loss = out + 2 * ROWS;
    float* abn_loss = out + 3 * ROWS;
    float* E        = out + 4 * ROWS;

    PFN_tmEnc enc = nullptr;
    cudaDriverEntryPointQueryResult qr;
    cudaGetDriverEntryPoint("cuTensorMapEncodeTiled", (void**)&enc,
                            cudaEnableDefault, &qr);
    void *pUh, *pUl, *pVh, *pVl, *pEh, *pEl, *pKh, *pKl;
    cudaGetSymbolAddress(&pUh, g_Uhi); cudaGetSymbolAddress(&pUl, g_Ulo);
    cudaGetSymbolAddress(&pVh, g_Vhi); cudaGetSymbolAddress(&pVl, g_Vlo);
    cudaGetSymbolAddress(&pEh, g_Ehi); cudaGetSymbolAddress(&pEl, g_Elo);
    cudaGetSymbolAddress(&pKh, g_Khi); cudaGetSymbolAddress(&pKl, g_Klo);

    CUtensorMap mUh, mUl, mVh, mVl, mEh, mEl, mKh, mKl;
    enc2d(enc, &mUh, pUh, DIN,  NPTS * GT,   (unsigned long long)DIN  * 2);
    enc2d(enc, &mUl, pUl, DIN,  NPTS * GT,   (unsigned long long)DIN  * 2);
    enc2d(enc, &mVh, pVh, DIN,  NPTS * DOUT, (unsigned long long)DIN  * 2);
    enc2d(enc, &mVl, pVl, DIN,  NPTS * DOUT, (unsigned long long)DIN  * 2);
    enc2d(enc, &mEh, pEh, DOUT, ROWS,        (unsigned long long)DOUT * 2);
    enc2d(enc, &mEl, pEl, DOUT, ROWS,        (unsigned long long)DOUT * 2);
    enc2d(enc, &mKh, pKh, DOUT, NKEYS,       (unsigned long long)DOUT * 2);
    enc2d(enc, &mKl, pKl, DOUT, NKEYS,       (unsigned long long)DOUT * 2);

    cudaFuncSetAttribute(wino_gemm_kernel,  cudaFuncAttributeMaxDynamicSharedMemorySize, SMEM_BYTES);
    cudaFuncSetAttribute(score_mma_kernel, cudaFuncAttributeMaxDynamicSharedMemorySize, SMEM_BYTES);

    wino_input_kernel<<<GT, 256>>>(ref_nor);
    wino_weight_kernel<<<(DOUT * DIN) / 256, 256>>>(conv_w);
    convert_keys_kernel<<<512, 256>>>(nor_keys, abn_keys);
    prep_keys_kernel<<<128, 256>>>(nor_keys, abn_keys, cls_mem_w);

    wino_gemm_kernel<<<dim3(4, 16, 6), 256, SMEM_BYTES>>>(mUh, mUl, mVh, mVl);
    wino_out_kernel<<<GT, 512>>>(conv_b, cls_w, cls_b, cls_mem_w, E, p_score);
    score_mma_kernel<<<dim3(8, 64), 256, SMEM_BYTES>>>(mEh, mEl, mKh, mKl);
    softmax_reduce_kernel<<<1024, 256>>>(cls_mem_b, up_score, nor_loss, abn_loss);
}

// round 7
// speedup vs baseline: 4.7252x; 1.0205x over previous
#include <cuda.h>
#include <cuda_runtime.h>
#include <cuda_fp16.h>
#include <math.h>
#include <stdint.h>

// Problem constants (B=32, N=256, D=2048, d=512, M=512)
#define ROWS  8192      // B*N
#define DIN   2048      // D
#define DOUT  512       // d
#define NKEYS 1024      // 2*M
#define NSEQ  256       // N
#define GT    2048      // B*64 winograd tiles
#define NPTS  6         // winograd F(4,3) points

// ---------------- scratch (device globals; no allocation allowed) ----------------
__device__ __align__(1024) __half g_Uhi[NPTS * GT * DIN];
__device__ __align__(1024) __half g_Ulo[NPTS * GT * DIN];
__device__ __align__(1024) __half g_Vhi[NPTS * DOUT * DIN];
__device__ __align__(1024) __half g_Vlo[NPTS * DOUT * DIN];
__device__ float g_M[(size_t)NPTS * GT * DOUT];
__device__ __align__(1024) __half g_Ehi[ROWS * DOUT];
__device__ __align__(1024) __half g_Elo[ROWS * DOUT];
__device__ __align__(1024) __half g_Khi[NKEYS * DOUT];
__device__ __align__(1024) __half g_Klo[NKEYS * DOUT];
__device__ float g_S[(size_t)ROWS * NKEYS];
__device__ float g_kv[NKEYS];
__device__ float g_kkn[NKEYS];
__device__ float g_w1dot[ROWS];
__device__ float g_qq[ROWS];

// ---------------- device helpers ----------------
__device__ __forceinline__ uint32_t smem_u32(const void* p) {
    uint32_t a;
    asm("{ .reg .u64 t; cvta.to.shared.u64 t, %1; cvt.u32.u64 %0, t; }" : "=r"(a) : "l"(p));
    return a;
}

#define MBARRIER_INIT(addr, cnt) \
    asm volatile("mbarrier.init.shared.b64 [%0], %1;" :: "r"((uint32_t)(addr)), "r"((uint32_t)(cnt)) : "memory")
#define MBARRIER_EXPECT_TX(addr, bytes) \
    asm volatile("mbarrier.arrive.expect_tx.shared.b64 _, [%0], %1;" :: "r"((uint32_t)(addr)), "r"((uint32_t)(bytes)) : "memory")
#define MBARRIER_WAIT_PARITY(addr, parity) do {                                        \
    uint32_t _m = (uint32_t)(addr); uint32_t _p = (uint32_t)(parity); uint32_t _d;     \
    asm volatile("{\n\t.reg .pred p;\n\t"                                              \
        "mbarrier.try_wait.parity.acquire.cta.shared::cta.b64 p, [%1], %2;\n\t"        \
        "selp.b32 %0, 1, 0, p;\n\t}"                                                   \
        : "=r"(_d) : "r"(_m), "r"(_p) : "memory");                                     \
    if (!_d) {                                                                         \
        asm volatile("{\n\t.reg .pred P1;\n\t"                                         \
            "WL_%=:\n\t"                                                               \
            "mbarrier.try_wait.parity.acquire.cta.shared::cta.b64 P1, [%0], %1, 0x989680;\n\t" \
            "@P1 bra.uni WD_%=;\n\t"                                                   \
            "bra.uni WL_%=;\n\t"                                                       \
            "WD_%=:\n\t}"                                                              \
            :: "r"(_m), "r"(_p) : "memory");                                           \
    }                                                                                  \
} while (0)

#define TMA_2D(smaddr, map, x, y, mbar) \
    asm volatile("cp.async.bulk.tensor.2d.shared::cta.global.tile.mbarrier::complete_tx::bytes " \
                 "[%0], [%1, {%2, %3}], [%4];" \
                 :: "r"((uint32_t)(smaddr)), "l"(map), "r"((int)(x)), "r"((int)(y)), \
                    "r"((uint32_t)(mbar)) : "memory")

#define LDMATRIX_X4(r0, r1, r2, r3, addr) \
    asm volatile("ldmatrix.sync.aligned.m8n8.x4.shared.b16 {%0,%1,%2,%3}, [%4];" \
                 : "=r"(r0), "=r"(r1), "=r"(r2), "=r"(r3) : "r"(addr))

// main pass: fp16 x fp16 -> fp32 accum
#define MMA_F16_F32(d, a, b0v, b1v) \
    asm volatile("mma.sync.aligned.m16n8k16.row.col.f32.f16.f16.f32 " \
                 "{%0,%1,%2,%3}, {%4,%5,%6,%7}, {%8,%9}, {%0,%1,%2,%3};" \
                 : "+f"((d)[0]), "+f"((d)[1]), "+f"((d)[2]), "+f"((d)[3]) \
                 : "r"((a)[0]), "r"((a)[1]), "r"((a)[2]), "r"((a)[3]), \
                   "r"(b0v), "r"(b1v))

// correction pass: fp16 x fp16 -> fp16 accum (packed f16x2 x2)
#define MMA_F16_F16(d, a, b0v, b1v) \
    asm volatile("mma.sync.aligned.m16n8k16.row.col.f16.f16.f16.f16 " \
                 "{%0,%1}, {%2,%3,%4,%5}, {%6,%7}, {%0,%1};" \
                 : "+r"((d)[0]), "+r"((d)[1]) \
                 : "r"((a)[0]), "r"((a)[1]), "r"((a)[2]), "r"((a)[3]), \
                   "r"(b0v), "r"(b1v))

__device__ __forceinline__ void split_f16(float x, uint32_t& h, uint32_t& l) {
    __half hb = __float2half_rn(x);
    float hf = __half2float(hb);
    __half lb = __float2half_rn(x - hf);
    h = (uint32_t)__half_as_ushort(hb);
    l = (uint32_t)__half_as_ushort(lb);
}

// pack two values into half2-as-u32 hi/lo words
__device__ __forceinline__ void split2_f16(float x0, float x1, uint32_t& hw, uint32_t& lw) {
    uint32_t h0, l0, h1, l1;
    split_f16(x0, h0, l0);
    split_f16(x1, h1, l1);
    hw = h0 | (h1 << 16);
    lw = l0 | (l1 << 16);
}

#define SW128(b) ((b) ^ (((b) >> 3) & 0x70))

// SMEM: barriers [0,24), stages at 1024 + s*65536. Matrices: AH, AL, BH, BL (16KB each).
#define STG_BASE   1024
#define STG_BYTES  65536
#define M_AH 0
#define M_AL 16384
#define M_BH 32768
#define M_BL 49152
#define NSTAGE 3
#define SMEM_BYTES (STG_BASE + NSTAGE * STG_BYTES)   // 197632

// ============================================================
// Winograd F(4,3) input transform: X -> U_p (fp16 hi/lo), channel pairs
// ============================================================
__global__ void wino_input_kernel(const float* __restrict__ X)
{
    const int gt = blockIdx.x;          // b*64 + t
    const int b = gt >> 6, t = gt & 63;
    const int n0 = 4 * t - 1;
#pragma unroll
    for (int cc = 0; cc < 4; cc++) {
        const int c = (threadIdx.x + cc * 256) * 2;
        float2 d[6];
#pragma unroll
        for (int i = 0; i < 6; i++) {
            const int n = n0 + i;
            d[i] = (n >= 0 && n < NSEQ)
                 ? *reinterpret_cast<const float2*>(X + ((size_t)b * NSEQ + n) * DIN + c)
                 : make_float2(0.f, 0.f);
        }
        float2 u[6];
        u[0].x =  4.f * d[0].x - 5.f * d[2].x + d[4].x;
        u[0].y =  4.f * d[0].y - 5.f * d[2].y + d[4].y;
        u[1].x = -4.f * (d[1].x + d[2].x) + d[3].x + d[4].x;
        u[1].y = -4.f * (d[1].y + d[2].y) + d[3].y + d[4].y;
        u[2].x =  4.f * d[1].x - 4.f * d[2].x - d[3].x + d[4].x;
        u[2].y =  4.f * d[1].y - 4.f * d[2].y - d[3].y + d[4].y;
        u[3].x = -2.f * d[1].x - d[2].x + 2.f * d[3].x + d[4].x;
        u[3].y = -2.f * d[1].y - d[2].y + 2.f * d[3].y + d[4].y;
        u[4].x =  2.f * d[1].x - d[2].x - 2.f * d[3].x + d[4].x;
        u[4].y =  2.f * d[1].y - d[2].y - 2.f * d[3].y + d[4].y;
        u[5].x =  4.f * d[1].x - 5.f * d[3].x + d[5].x;
        u[5].y =  4.f * d[1].y - 5.f * d[3].y + d[5].y;
#pragma unroll
        for (int p = 0; p < 6; p++) {
            uint32_t hw, lw;
            split2_f16(u[p].x, u[p].y, hw, lw);
            const size_t off = ((size_t)(p * GT + gt)) * DIN + c;
            *reinterpret_cast<uint32_t*>(g_Uhi + off) = hw;
            *reinterpret_cast<uint32_t*>(g_Ulo + off) = lw;
        }
    }
}

// ============================================================
// Winograd weight transform: conv_w (o, c, 3) -> V_p[o][c], channel pairs
// ============================================================
__global__ void wino_weight_kernel(const float* __restrict__ conv_w)
{
    const int pidx = blockIdx.x * 256 + threadIdx.x;  // pair index: o*1024 + c/2
    const int o = pidx >> 10, cp = pidx & 1023;
    const int c = cp * 2;
    const size_t base = (size_t)o * (DIN * 3) + (size_t)c * 3;
    const float w0a = conv_w[base + 0], w1a = conv_w[base + 1], w2a = conv_w[base + 2];
    const float w0b = conv_w[base + 3], w1b = conv_w[base + 4], w2b = conv_w[base + 5];
    float va[6], vb[6];
    va[0] =  0.25f * w0a;                          vb[0] =  0.25f * w0b;
    va[1] = -(w0a + w1a + w2a) * (1.f / 6.f);      vb[1] = -(w0b + w1b + w2b) * (1.f / 6.f);
    va[2] = (-w0a + w1a - w2a) * (1.f / 6.f);      vb[2] = (-w0b + w1b - w2b) * (1.f / 6.f);
    va[3] =  w0a * (1.f / 24.f) + w1a * (1.f / 12.f) + w2a * (1.f / 6.f);
    vb[3] =  w0b * (1.f / 24.f) + w1b * (1.f / 12.f) + w2b * (1.f / 6.f);
    va[4] =  w0a * (1.f / 24.f) - w1a * (1.f / 12.f) + w2a * (1.f / 6.f);
    vb[4] =  w0b * (1.f / 24.f) - w1b * (1.f / 12.f) + w2b * (1.f / 6.f);
    va[5] =  w2a;                                  vb[5] =  w2b;
#pragma unroll
    for (int p = 0; p < 6; p++) {
        uint32_t hw, lw;
        split2_f16(va[p], vb[p], hw, lw);
        const size_t off = ((size_t)(p * DOUT + o)) * DIN + c;
        *reinterpret_cast<uint32_t*>(g_Vhi + off) = hw;
        *reinterpret_cast<uint32_t*>(g_Vlo + off) = lw;
    }
}

// ============================================================
// fused keys: convert to fp16 hi/lo + kv/kkn reductions (one read of keys)
// ============================================================
__global__ void keys_kernel(const float* __restrict__ nor_keys,
                            const float* __restrict__ abn_keys,
                            const float* __restrict__ cls_mem_w) {
    const int j = blockIdx.x * 8 + (threadIdx.x >> 5);
    const int lane = threadIdx.x & 31;
    const float* key = (j < 512) ? (nor_keys + (size_t)j * DOUT)
                                 : (abn_keys + (size_t)(j - 512) * DOUT);
    const float* w2 = cls_mem_w + DOUT;
    float kv = 0.f, kn = 0.f;
#pragma unroll
    for (int t = 0; t < 4; t++) {
        const int c = (lane + t * 32) * 4;
        float4 k4 = *reinterpret_cast<const float4*>(key + c);
        float4 w4 = *reinterpret_cast<const float4*>(w2 + c);
        kv += k4.x * w4.x + k4.y * w4.y + k4.z * w4.z + k4.w * w4.w;
        kn += k4.x * k4.x + k4.y * k4.y + k4.z * k4.z + k4.w * k4.w;
        uint32_t hw0, lw0, hw1, lw1;
        split2_f16(k4.x, k4.y, hw0, lw0);
        split2_f16(k4.z, k4.w, hw1, lw1);
        const size_t e = (size_t)j * DOUT + c;
        *reinterpret_cast<uint2*>(g_Khi + e) = make_uint2(hw0, hw1);
        *reinterpret_cast<uint2*>(g_Klo + e) = make_uint2(lw0, lw1);
    }
#pragma unroll
    for (int o = 16; o; o >>= 1) {
        kv += __shfl_xor_sync(0xffffffffu, kv, o);
        kn += __shfl_xor_sync(0xffffffffu, kn, o);
    }
    if (lane == 0) { g_kv[j] = kv; g_kkn[j] = kn; }
}

// ============================================================
// 2.5-pass fp16 MMA over one 128x128x64 chunk in SW128 SMEM.
// ============================================================
__device__ __forceinline__ void mma_chunk_sw(uint32_t st,
                                             float accf[2][8][4],
                                             uint32_t acch[2][8][2],
                                             int wm, int wn, int lane)
{
    const int lrow  = lane & 15;
    const int khalf = lane >> 4;
#pragma unroll
    for (int ks = 0; ks < 4; ks++) {
        const uint32_t kb = ks * 32 + khalf * 16;
        uint32_t ah[2][4], al[2][4];
#pragma unroll
        for (int mf = 0; mf < 2; mf++) {
            const uint32_t ro = (uint32_t)((wm + mf * 16 + lrow) * 128) + kb;
            LDMATRIX_X4(ah[mf][0], ah[mf][1], ah[mf][2], ah[mf][3], st + M_AH + SW128(ro));
            LDMATRIX_X4(al[mf][0], al[mf][1], al[mf][2], al[mf][3], st + M_AL + SW128(ro));
        }
        uint32_t bh[4][4], bl[4][4];
#pragma unroll
        for (int nq = 0; nq < 4; nq++) {
            const uint32_t ro = (uint32_t)((wn + nq * 16 + lrow) * 128) + kb;
            LDMATRIX_X4(bh[nq][0], bh[nq][1], bh[nq][2], bh[nq][3], st + M_BH + SW128(ro));
            LDMATRIX_X4(bl[nq][0], bl[nq][1], bl[nq][2], bl[nq][3], st + M_BL + SW128(ro));
        }
#pragma unroll
        for (int mf = 0; mf < 2; mf++)
#pragma unroll
            for (int nq = 0; nq < 4; nq++)
#pragma unroll
                for (int nh = 0; nh < 2; nh++) {
                    MMA_F16_F32(accf[mf][nq * 2 + nh], ah[mf], bh[nq][nh], bh[nq][nh + 2]);
                    MMA_F16_F16(acch[mf][nq * 2 + nh], ah[mf], bl[nq][nh], bl[nq][nh + 2]);
                    MMA_F16_F16(acch[mf][nq * 2 + nh], al[mf], bh[nq][nh], bh[nq][nh + 2]);
                }
    }
}

__device__ __forceinline__ float frag_val(const float accf[4], const uint32_t acch[2], int idx) {
    const __half2 c = *reinterpret_cast<const __half2*>(&acch[idx >> 1]);
    const float corr = (idx & 1) ? __high2float(c) : __low2float(c);
    return accf[idx] + corr;
}

// ============================================================
// Winograd GEMM: M_p = U_p @ V_p^T  (6 points, 2048x512x2048 each)
// ============================================================
__global__ void __launch_bounds__(256, 1) wino_gemm_kernel(
    const __grid_constant__ CUtensorMap mUh,
    const __grid_constant__ CUtensorMap mUl,
    const __grid_constant__ CUtensorMap mVh,
    const __grid_constant__ CUtensorMap mVl)
{
    extern __shared__ char smem[];
    const uint32_t sb = smem_u32(smem);
    const int tid  = threadIdx.x;
    const int wid  = tid >> 5;
    const int lane = tid & 31;
    const int bm = blockIdx.y * 128;
    const int bn = blockIdx.x * 128;
    const int p  = blockIdx.z;
    const int wm = (wid >> 1) * 32;
    const int wn = (wid & 1) * 64;

    float    accf[2][8][4];
    uint32_t acch[2][8][2];
#pragma unroll
    for (int i = 0; i < 2; i++)
#pragma unroll
        for (int j = 0; j < 8; j++) {
#pragma unroll
            for (int c = 0; c < 4; c++) accf[i][j][c] = 0.f;
            acch[i][j][0] = 0u; acch[i][j][1] = 0u;
        }

    if (tid == 0) {
        MBARRIER_INIT(sb + 0, 1);
        MBARRIER_INIT(sb + 8, 1);
        MBARRIER_INIT(sb + 16, 1);
    }
    __syncthreads();

    const int CHUNKS = DIN / 64;   // 32
    auto issue = [&](int i) {
        const int s = i % NSTAGE;
        const uint32_t st = sb + STG_BASE + s * STG_BYTES;
        const uint32_t mb = sb + s * 8;
        const int k0 = i * 64;
        MBARRIER_EXPECT_TX(mb, STG_BYTES);
        TMA_2D(st + M_AH, &mUh, k0, p * GT + bm, mb);
        TMA_2D(st + M_AL, &mUl, k0, p * GT + bm, mb);
        TMA_2D(st + M_BH, &mVh, k0, p * DOUT + bn, mb);
        TMA_2D(st + M_BL, &mVl, k0, p * DOUT + bn, mb);
    };
    if (tid == 0) { issue(0); issue(1); issue(2); }

    for (int i = 0; i < CHUNKS; i++) {
        const int s = i % NSTAGE;
        MBARRIER_WAIT_PARITY(sb + s * 8, (uint32_t)((i / NSTAGE) & 1));
        mma_chunk_sw(sb + STG_BASE + s * STG_BYTES, accf, acch, wm, wn, lane);
        __syncthreads();
        if (tid == 0 && i + NSTAGE < CHUNKS) issue(i + NSTAGE);
    }

#pragma unroll
    for (int mf = 0; mf < 2; mf++) {
        const int row0 = bm + wm + mf * 16 + (lane >> 2);
#pragma unroll
        for (int nf = 0; nf < 8; nf++) {
            const int col = bn + wn + nf * 8 + (lane & 3) * 2;
#pragma unroll
            for (int h = 0; h < 2; h++) {
                const int row = row0 + h * 8;
                *reinterpret_cast<float2*>(
                    g_M + ((size_t)(p * GT) + row) * DOUT + col) =
                    make_float2(frag_val(accf[mf][nf], acch[mf][nf], 2 * h),
                                frag_val(accf[mf][nf], acch[mf][nf], 2 * h + 1));
            }
        }
    }
}

// ============================================================
// Winograd output transform + bias + relu -> E (fp32 + fp16 hi/lo)
// fused rowstats. One block per tile gt, 256 threads x 2 outputs.
// ============================================================
__global__ void __launch_bounds__(256) wino_out_kernel(
    const float* __restrict__ bias,
    const float* __restrict__ cls_w,
    const float* __restrict__ cls_b,
    const float* __restrict__ cls_mem_w,
    float* __restrict__ E,
    float* __restrict__ p_out)
{
    const int gt = blockIdx.x;
    const int o  = threadIdx.x * 2;
    float2 m[6];
#pragma unroll
    for (int p = 0; p < 6; p++)
        m[p] = *reinterpret_cast<const float2*>(g_M + ((size_t)(p * GT) + gt) * DOUT + o);

    float ya[4], yb[4];
    ya[0] = m[0].x + m[1].x + m[2].x + m[3].x + m[4].x;
    yb[0] = m[0].y + m[1].y + m[2].y + m[3].y + m[4].y;
    ya[1] = m[1].x - m[2].x + 2.f * (m[3].x - m[4].x);
    yb[1] = m[1].y - m[2].y + 2.f * (m[3].y - m[4].y);
    ya[2] = m[1].x + m[2].x + 4.f * (m[3].x + m[4].x);
    yb[2] = m[1].y + m[2].y + 4.f * (m[3].y + m[4].y);
    ya[3] = m[1].x - m[2].x + 8.f * (m[3].x - m[4].x) + m[5].x;
    yb[3] = m[1].y - m[2].y + 8.f * (m[3].y - m[4].y) + m[5].y;

    const float2 b  = *reinterpret_cast<const float2*>(bias + o);
    const float2 w0 = *reinterpret_cast<const float2*>(cls_w + o);
    const float2 w1 = *reinterpret_cast<const float2*>(cls_mem_w + o);

    __shared__ float red[8][12];
    const int lane = threadIdx.x & 31, wrp = threadIdx.x >> 5;

    float d0[4], d1[4], qq[4];
#pragma unroll
    for (int r = 0; r < 4; r++) {
        const float v0 = fmaxf(ya[r] + b.x, 0.f);
        const float v1 = fmaxf(yb[r] + b.y, 0.f);
        const int row = 4 * gt + r;
        *reinterpret_cast<float2*>(E + (size_t)row * DOUT + o) = make_float2(v0, v1);
        uint32_t hw, lw;
        split2_f16(v0, v1, hw, lw);
        *reinterpret_cast<uint32_t*>(g_Ehi + (size_t)row * DOUT + o) = hw;
        *reinterpret_cast<uint32_t*>(g_Elo + (size_t)row * DOUT + o) = lw;
        d0[r] = v0 * w0.x + v1 * w0.y;
        d1[r] = v0 * w1.x + v1 * w1.y;
        qq[r] = v0 * v0 + v1 * v1;
    }
#pragma unroll
    for (int r = 0; r < 4; r++) {
#pragma unroll
        for (int off = 16; off; off >>= 1) {
            d0[r] += __shfl_xor_sync(0xffffffffu, d0[r], off);
            d1[r] += __shfl_xor_sync(0xffffffffu, d1[r], off);
            qq[r] += __shfl_xor_sync(0xffffffffu, qq[r], off);
        }
        if (lane == 0) {
            red[wrp][3 * r + 0] = d0[r];
            red[wrp][3 * r + 1] = d1[r];
            red[wrp][3 * r + 2] = qq[r];
        }
    }
    __syncthreads();
    if (threadIdx.x < 12) {
        float s = 0.f;
#pragma unroll
        for (int w = 0; w < 8; w++) s += red[w][threadIdx.x];
        const int r = threadIdx.x / 3, q = threadIdx.x - 3 * r;
        const int row = 4 * gt + r;
        if (q == 0)      p_out[row]   = 1.f / (1.f + __expf(-(s + cls_b[0])));
        else if (q == 1) g_w1dot[row] = s;
        else             g_qq[row]    = s;
    }
}

// ============================================================
// score GEMM: S = E @ keys^T, tile 128x128, K=512, TMA feed
// ============================================================
__global__ void __launch_bounds__(256, 1) score_mma_kernel(
    const __grid_constant__ CUtensorMap mEh,
    const __grid_constant__ CUtensorMap mEl,
    const __grid_constant__ CUtensorMap mKh,
    const __grid_constant__ CUtensorMap mKl)
{
    extern __shared__ char smem[];
    const uint32_t sb = smem_u32(smem);
    const int tid  = threadIdx.x;
    const int wid  = tid >> 5;
    const int lane = tid & 31;
    const int bm = blockIdx.y * 128;
    const int bn = blockIdx.x * 128;
    const int wm = (wid >> 1) * 32;
    const int wn = (wid & 1) * 64;

    float    accf[2][8][4];
    uint32_t acch[2][8][2];
#pragma unroll
    for (int i = 0; i < 2; i++)
#pragma unroll
        for (int j = 0; j < 8; j++) {
#pragma unroll
            for (int c = 0; c < 4; c++) accf[i][j][c] = 0.f;
            acch[i][j][0] = 0u; acch[i][j][1] = 0u;
        }

    if (tid == 0) {
        MBARRIER_INIT(sb + 0, 1);
        MBARRIER_INIT(sb + 8, 1);
        MBARRIER_INIT(sb + 16, 1);
    }
    __syncthreads();

    const int CHUNKS = DOUT / 64;   // 8
    auto issue = [&](int i) {
        const int s = i % NSTAGE;
        const uint32_t st = sb + STG_BASE + s * STG_BYTES;
        const uint32_t mb = sb + s * 8;
        const int k0 = i * 64;
        MBARRIER_EXPECT_TX(mb, STG_BYTES);
        TMA_2D(st + M_AH, &mEh, k0, bm, mb);
        TMA_2D(st + M_AL, &mEl, k0, bm, mb);
        TMA_2D(st + M_BH, &mKh, k0, bn, mb);
        TMA_2D(st + M_BL, &mKl, k0, bn, mb);
    };
    if (tid == 0) { issue(0); issue(1); issue(2); }

    for (int i = 0; i < CHUNKS; i++) {
        const int s = i % NSTAGE;
        MBARRIER_WAIT_PARITY(sb + s * 8, (uint32_t)((i / NSTAGE) & 1));
        mma_chunk_sw(sb + STG_BASE + s * STG_BYTES, accf, acch, wm, wn, lane);
        __syncthreads();
        if (tid == 0 && i + NSTAGE < CHUNKS) issue(i + NSTAGE);
    }

#pragma unroll
    for (int mf = 0; mf < 2; mf++) {
        const int row0 = bm + wm + mf * 16 + (lane >> 2);
#pragma unroll
        for (int nf = 0; nf < 8; nf++) {
            const int col = bn + wn + nf * 8 + (lane & 3) * 2;
#pragma unroll
            for (int h = 0; h < 2; h++) {
                const int row = row0 + h * 8;
                *reinterpret_cast<float2*>(g_S + (size_t)row * NKEYS + col) =
                    make_float2(frag_val(accf[mf][nf], acch[mf][nf], 2 * h),
                                frag_val(accf[mf][nf], acch[mf][nf], 2 * h + 1));
            }
        }
    }
}

// ============================================================
// softmax / argmax reduction over S rows
// ============================================================
__global__ void softmax_reduce_kernel(const float* __restrict__ cls_mem_b,
                                      float* __restrict__ up_out,
                                      float* __restrict__ nor_out,
                                      float* __restrict__ abn_out)
{
    const int row  = blockIdx.x * 8 + (threadIdx.x >> 5);
    const int lane = threadIdx.x & 31;
    const float* Sr = g_S + (size_t)row * NKEYS;

    float s[32];
    float m = -INFINITY;
    float bv0 = -INFINITY, bv1 = -INFINITY;
    int bi0 = 0, bi1 = 0;
#pragma unroll
    for (int t = 0; t < 32; t++) {
        const int j = t * 32 + lane;
        const float v = Sr[j];
        s[t] = v;
        m = fmaxf(m, v);
        if (t < 16) { if (v > bv0) { bv0 = v; bi0 = j; } }
        else        { if (v > bv1) { bv1 = v; bi1 = j; } }
    }
#pragma unroll
    for (int o = 16; o; o >>= 1) m = fmaxf(m, __shfl_xor_sync(0xffffffffu, m, o));

    float l = 0.f, dsum = 0.f;
#pragma unroll
    for (int t = 0; t < 32; t++) {
        const int j = t * 32 + lane;
        const float e = __expf(s[t] - m);
        l += e;
        dsum += e * g_kv[j];
    }
#pragma unroll
    for (int o = 16; o; o >>= 1) {
        l    += __shfl_xor_sync(0xffffffffu, l, o);
        dsum += __shfl_xor_sync(0xffffffffu, dsum, o);
    }
#pragma unroll
    for (int o = 16; o; o >>= 1) {
        const float o0 = __shfl_xor_sync(0xffffffffu, bv0, o);
        const int   i0 = __shfl_xor_sync(0xffffffffu, bi0, o);
        if (o0 > bv0 || (o0 == bv0 && i0 < bi0)) { bv0 = o0; bi0 = i0; }
        const float o1 = __shfl_xor_sync(0xffffffffu, bv1, o);
        const int   i1 = __shfl_xor_sync(0xffffffffu, bi1, o);
        if (o1 > bv1 || (o1 == bv1 && i1 < bi1)) { bv1 = o1; bi1 = i1; }
    }
    if (lane == 0) {
        const float x = g_w1dot[row] + dsum / l + cls_mem_b[0];
        up_out[row] = 1.f / (1.f + __expf(-x));
        const float qq = g_qq[row];
        nor_out[row] = (qq - 2.f * bv0 + g_kkn[bi0]) * (1.f / 512.f);
        abn_out[row] = (qq - 2.f * bv1 + g_kkn[bi1]) * (1.f / 512.f);
    }
}

// ============================================================
// host: tensormap construction (driver entry point via cudart; no -lcuda)
// ============================================================
typedef CUresult (*PFN_tmEnc)(CUtensorMap*, CUtensorMapDataType, cuuint32_t, void*,
                              const cuuint64_t*, const cuuint64_t*, const cuuint32_t*,
                              const cuuint32_t*, CUtensorMapInterleave, CUtensorMapSwizzle,
                              CUtensorMapL2promotion, CUtensorMapFloatOOBfill);

static void enc2d(PFN_tmEnc f, CUtensorMap* m, void* addr,
                  unsigned long long d0, unsigned long long d1,
                  unsigned long long stride_bytes)
{
    cuuint64_t dims[2]    = {(cuuint64_t)d0, (cuuint64_t)d1};
    cuuint64_t strides[1] = {(cuuint64_t)stride_bytes};
    cuuint32_t box[2]     = {64u, 128u};
    cuuint32_t es[2]      = {1u, 1u};
    f(m, CU_TENSOR_MAP_DATA_TYPE_FLOAT16, 2, addr, dims, strides, box, es,
      CU_TENSOR_MAP_INTERLEAVE_NONE, CU_TENSOR_MAP_SWIZZLE_128B,
      CU_TENSOR_MAP_L2_PROMOTION_L2_128B, CU_TENSOR_MAP_FLOAT_OOB_FILL_NONE);
}

extern "C" void kernel_launch(void* const* d_in, const int* in_sizes, int n_in,
                              void* d_out, int out_size)
{
    const float* ref_nor   = (const float*)d_in[0];
    // d_in[1] = ref_abn : dead (only feeds the discarded p_score[B:])
    const float* nor_keys  = (const float*)d_in[2];
    const float* abn_keys  = (const float*)d_in[3];
    const float* conv_w    = (const float*)d_in[4];
    const float* conv_b    = (const float*)d_in[5];
    const float* cls_w     = (const float*)d_in[6];
    const float* cls_b     = (const float*)d_in[7];
    const float* cls_mem_w = (const float*)d_in[8];
    const float* cls_mem_b = (const float*)d_in[9];

    float* out      = (float*)d_out;
    float* p_score  = out;
    float* up_score = out + ROWS;
    float* nor_loss = out + 2 * ROWS;
    float* abn_loss = out + 3 * ROWS;
    float* E        = out + 4 * ROWS;

    PFN_tmEnc enc = nullptr;
    cudaDriverEntryPointQueryResult qr;
    cudaGetDriverEntryPoint("cuTensorMapEncodeTiled", (void**)&enc,
                            cudaEnableDefault, &qr);
    void *pUh, *pUl, *pVh, *pVl, *pEh, *pEl, *pKh, *pKl;
    cudaGetSymbolAddress(&pUh, g_Uhi); cudaGetSymbolAddress(&pUl, g_Ulo);
    cudaGetSymbolAddress(&pVh, g_Vhi); cudaGetSymbolAddress(&pVl, g_Vlo);
    cudaGetSymbolAddress(&pEh, g_Ehi); cudaGetSymbolAddress(&pEl, g_Elo);
    cudaGetSymbolAddress(&pKh, g_Khi); cudaGetSymbolAddress(&pKl, g_Klo);

    CUtensorMap mUh, mUl, mVh, mVl, mEh, mEl, mKh, mKl;
    enc2d(enc, &mUh, pUh, DIN,  NPTS * GT,   (unsigned long long)DIN  * 2);
    enc2d(enc, &mUl, pUl, DIN,  NPTS * GT,   (unsigned long long)DIN  * 2);
    enc2d(enc, &mVh, pVh, DIN,  NPTS * DOUT, (unsigned long long)DIN  * 2);
    enc2d(enc, &mVl, pVl, DIN,  NPTS * DOUT, (unsigned long long)DIN  * 2);
    enc2d(enc, &mEh, pEh, DOUT, ROWS,        (unsigned long long)DOUT * 2);
    enc2d(enc, &mEl, pEl, DOUT, ROWS,        (unsigned long long)DOUT * 2);
    enc2d(enc, &mKh, pKh, DOUT, NKEYS,       (unsigned long long)DOUT * 2);
    enc2d(enc, &mKl, pKl, DOUT, NKEYS,       (unsigned long long)DOUT * 2);

    cudaFuncSetAttribute(wino_gemm_kernel,  cudaFuncAttributeMaxDynamicSharedMemorySize, SMEM_BYTES);
    cudaFuncSetAttribute(score_mma_kernel, cudaFuncAttributeMaxDynamicSharedMemorySize, SMEM_BYTES);

    wino_weight_kernel<<<(DOUT * DIN / 2) / 256, 256>>>(conv_w);
    wino_input_kernel<<<GT, 256>>>(ref_nor);
    keys_kernel<<<128, 256>>>(nor_keys, abn_keys, cls_mem_w);

    wino_gemm_kernel<<<dim3(4, 16, 6), 256, SMEM_BYTES>>>(mUh, mUl, mVh, mVl);
    wino_out_kernel<<<GT, 256>>>(conv_b, cls_w, cls_b, cls_mem_w, E, p_score);
    score_mma_kernel<<<dim3(8, 64), 256, SMEM_BYTES>>>(mEh, mEl, mKh, mKl);
    softmax_reduce_kernel<<<1024, 256>>>(cls_mem_b, up_score, nor_loss, abn_loss);
}

// round 8
// speedup vs baseline: 4.7530x; 1.0059x over previous
#include <cuda.h>
#include <cuda_runtime.h>
#include <cuda_fp16.h>
#include <math.h>
#include <stdint.h>

// Problem constants (B=32, N=256, D=2048, d=512, M=512)
#define ROWS  8192      // B*N
#define DIN   2048      // D
#define DOUT  512       // d
#define NKEYS 1024      // 2*M
#define NSEQ  256       // N
#define GT    2048      // B*64 winograd tiles
#define NPTS  6         // winograd F(4,3) points

// ---------------- scratch (device globals; no allocation allowed) ----------------
__device__ __align__(1024) __half g_Uhi[NPTS * GT * DIN];
__device__ __align__(1024) __half g_Ulo[NPTS * GT * DIN];
__device__ __align__(1024) __half g_Vhi[NPTS * DOUT * DIN];
__device__ __align__(1024) __half g_Vlo[NPTS * DOUT * DIN];
__device__ float g_M[(size_t)NPTS * GT * DOUT];
__device__ __align__(1024) __half g_Ehi[ROWS * DOUT];
__device__ __align__(1024) __half g_Elo[ROWS * DOUT];
__device__ __align__(1024) __half g_Khi[NKEYS * DOUT];
__device__ __align__(1024) __half g_Klo[NKEYS * DOUT];
__device__ float g_S[(size_t)ROWS * NKEYS];
__device__ float g_kv[NKEYS];
__device__ float g_kkn[NKEYS];
__device__ float g_w1dot[ROWS];
__device__ float g_qq[ROWS];

// ---------------- device helpers ----------------
__device__ __forceinline__ uint32_t smem_u32(const void* p) {
    uint32_t a;
    asm("{ .reg .u64 t; cvta.to.shared.u64 t, %1; cvt.u32.u64 %0, t; }" : "=r"(a) : "l"(p));
    return a;
}

#define MBARRIER_INIT(addr, cnt) \
    asm volatile("mbarrier.init.shared.b64 [%0], %1;" :: "r"((uint32_t)(addr)), "r"((uint32_t)(cnt)) : "memory")
#define MBARRIER_EXPECT_TX(addr, bytes) \
    asm volatile("mbarrier.arrive.expect_tx.shared.b64 _, [%0], %1;" :: "r"((uint32_t)(addr)), "r"((uint32_t)(bytes)) : "memory")
#define MBARRIER_WAIT_PARITY(addr, parity) do {                                        \
    uint32_t _m = (uint32_t)(addr); uint32_t _p = (uint32_t)(parity); uint32_t _d;     \
    asm volatile("{\n\t.reg .pred p;\n\t"                                              \
        "mbarrier.try_wait.parity.acquire.cta.shared::cta.b64 p, [%1], %2;\n\t"        \
        "selp.b32 %0, 1, 0, p;\n\t}"                                                   \
        : "=r"(_d) : "r"(_m), "r"(_p) : "memory");                                     \
    if (!_d) {                                                                         \
        asm volatile("{\n\t.reg .pred P1;\n\t"                                         \
            "WL_%=:\n\t"                                                               \
            "mbarrier.try_wait.parity.acquire.cta.shared::cta.b64 P1, [%0], %1, 0x989680;\n\t" \
            "@P1 bra.uni WD_%=;\n\t"                                                   \
            "bra.uni WL_%=;\n\t"                                                       \
            "WD_%=:\n\t}"                                                              \
            :: "r"(_m), "r"(_p) : "memory");                                           \
    }                                                                                  \
} while (0)

#define TMA_2D(smaddr, map, x, y, mbar) \
    asm volatile("cp.async.bulk.tensor.2d.shared::cta.global.tile.mbarrier::complete_tx::bytes " \
                 "[%0], [%1, {%2, %3}], [%4];" \
                 :: "r"((uint32_t)(smaddr)), "l"(map), "r"((int)(x)), "r"((int)(y)), \
                    "r"((uint32_t)(mbar)) : "memory")

#define LDMATRIX_X4(r0, r1, r2, r3, addr) \
    asm volatile("ldmatrix.sync.aligned.m8n8.x4.shared.b16 {%0,%1,%2,%3}, [%4];" \
                 : "=r"(r0), "=r"(r1), "=r"(r2), "=r"(r3) : "r"(addr))

// main pass: fp16 x fp16 -> fp32 accum
#define MMA_F16_F32(d, a, b0v, b1v) \
    asm volatile("mma.sync.aligned.m16n8k16.row.col.f32.f16.f16.f32 " \
                 "{%0,%1,%2,%3}, {%4,%5,%6,%7}, {%8,%9}, {%0,%1,%2,%3};" \
                 : "+f"((d)[0]), "+f"((d)[1]), "+f"((d)[2]), "+f"((d)[3]) \
                 : "r"((a)[0]), "r"((a)[1]), "r"((a)[2]), "r"((a)[3]), \
                   "r"(b0v), "r"(b1v))

// correction pass: fp16 x fp16 -> fp16 accum (packed f16x2 x2)
#define MMA_F16_F16(d, a, b0v, b1v) \
    asm volatile("mma.sync.aligned.m16n8k16.row.col.f16.f16.f16.f16 " \
                 "{%0,%1}, {%2,%3,%4,%5}, {%6,%7}, {%0,%1};" \
                 : "+r"((d)[0]), "+r"((d)[1]) \
                 : "r"((a)[0]), "r"((a)[1]), "r"((a)[2]), "r"((a)[3]), \
                   "r"(b0v), "r"(b1v))

__device__ __forceinline__ void split_f16(float x, uint32_t& h, uint32_t& l) {
    __half hb = __float2half_rn(x);
    float hf = __half2float(hb);
    __half lb = __float2half_rn(x - hf);
    h = (uint32_t)__half_as_ushort(hb);
    l = (uint32_t)__half_as_ushort(lb);
}

__device__ __forceinline__ void split2_f16(float x0, float x1, uint32_t& hw, uint32_t& lw) {
    uint32_t h0, l0, h1, l1;
    split_f16(x0, h0, l0);
    split_f16(x1, h1, l1);
    hw = h0 | (h1 << 16);
    lw = l0 | (l1 << 16);
}

#define SW128(b) ((b) ^ (((b) >> 3) & 0x70))

// SMEM: barriers [0,24), stages at 1024 + s*65536. Matrices: AH, AL, BH, BL (16KB each).
#define STG_BASE   1024
#define STG_BYTES  65536
#define M_AH 0
#define M_AL 16384
#define M_BH 32768
#define M_BL 49152
#define NSTAGE 3
#define SMEM_BYTES (STG_BASE + NSTAGE * STG_BYTES)   // 197632

// ============================================================
// Winograd F(4,3) input transform: X -> U_p (fp16 hi/lo), channel pairs
// ============================================================
__global__ void wino_input_kernel(const float* __restrict__ X)
{
    const int gt = blockIdx.x;          // b*64 + t
    const int b = gt >> 6, t = gt & 63;
    const int n0 = 4 * t - 1;
#pragma unroll
    for (int cc = 0; cc < 4; cc++) {
        const int c = (threadIdx.x + cc * 256) * 2;
        float2 d[6];
#pragma unroll
        for (int i = 0; i < 6; i++) {
            const int n = n0 + i;
            d[i] = (n >= 0 && n < NSEQ)
                 ? *reinterpret_cast<const float2*>(X + ((size_t)b * NSEQ + n) * DIN + c)
                 : make_float2(0.f, 0.f);
        }
        float2 u[6];
        u[0].x =  4.f * d[0].x - 5.f * d[2].x + d[4].x;
        u[0].y =  4.f * d[0].y - 5.f * d[2].y + d[4].y;
        u[1].x = -4.f * (d[1].x + d[2].x) + d[3].x + d[4].x;
        u[1].y = -4.f * (d[1].y + d[2].y) + d[3].y + d[4].y;
        u[2].x =  4.f * d[1].x - 4.f * d[2].x - d[3].x + d[4].x;
        u[2].y =  4.f * d[1].y - 4.f * d[2].y - d[3].y + d[4].y;
        u[3].x = -2.f * d[1].x - d[2].x + 2.f * d[3].x + d[4].x;
        u[3].y = -2.f * d[1].y - d[2].y + 2.f * d[3].y + d[4].y;
        u[4].x =  2.f * d[1].x - d[2].x - 2.f * d[3].x + d[4].x;
        u[4].y =  2.f * d[1].y - d[2].y - 2.f * d[3].y + d[4].y;
        u[5].x =  4.f * d[1].x - 5.f * d[3].x + d[5].x;
        u[5].y =  4.f * d[1].y - 5.f * d[3].y + d[5].y;
#pragma unroll
        for (int p = 0; p < 6; p++) {
            uint32_t hw, lw;
            split2_f16(u[p].x, u[p].y, hw, lw);
            const size_t off = ((size_t)(p * GT + gt)) * DIN + c;
            *reinterpret_cast<uint32_t*>(g_Uhi + off) = hw;
            *reinterpret_cast<uint32_t*>(g_Ulo + off) = lw;
        }
    }
}

// ============================================================
// Winograd weight transform: conv_w (o, c, 3) -> V_p[o][c], channel pairs
// ============================================================
__global__ void wino_weight_kernel(const float* __restrict__ conv_w)
{
    const int pidx = blockIdx.x * 256 + threadIdx.x;  // pair index: o*1024 + c/2
    const int o = pidx >> 10, cp = pidx & 1023;
    const int c = cp * 2;
    const size_t base = (size_t)o * (DIN * 3) + (size_t)c * 3;
    const float w0a = conv_w[base + 0], w1a = conv_w[base + 1], w2a = conv_w[base + 2];
    const float w0b = conv_w[base + 3], w1b = conv_w[base + 4], w2b = conv_w[base + 5];
    float va[6], vb[6];
    va[0] =  0.25f * w0a;                          vb[0] =  0.25f * w0b;
    va[1] = -(w0a + w1a + w2a) * (1.f / 6.f);      vb[1] = -(w0b + w1b + w2b) * (1.f / 6.f);
    va[2] = (-w0a + w1a - w2a) * (1.f / 6.f);      vb[2] = (-w0b + w1b - w2b) * (1.f / 6.f);
    va[3] =  w0a * (1.f / 24.f) + w1a * (1.f / 12.f) + w2a * (1.f / 6.f);
    vb[3] =  w0b * (1.f / 24.f) + w1b * (1.f / 12.f) + w2b * (1.f / 6.f);
    va[4] =  w0a * (1.f / 24.f) - w1a * (1.f / 12.f) + w2a * (1.f / 6.f);
    vb[4] =  w0b * (1.f / 24.f) - w1b * (1.f / 12.f) + w2b * (1.f / 6.f);
    va[5] =  w2a;                                  vb[5] =  w2b;
#pragma unroll
    for (int p = 0; p < 6; p++) {
        uint32_t hw, lw;
        split2_f16(va[p], vb[p], hw, lw);
        const size_t off = ((size_t)(p * DOUT + o)) * DIN + c;
        *reinterpret_cast<uint32_t*>(g_Vhi + off) = hw;
        *reinterpret_cast<uint32_t*>(g_Vlo + off) = lw;
    }
}

// ============================================================
// fused keys: convert to fp16 hi/lo + kv/kkn reductions
// ============================================================
__global__ void keys_kernel(const float* __restrict__ nor_keys,
                            const float* __restrict__ abn_keys,
                            const float* __restrict__ cls_mem_w) {
    const int j = blockIdx.x * 8 + (threadIdx.x >> 5);
    const int lane = threadIdx.x & 31;
    const float* key = (j < 512) ? (nor_keys + (size_t)j * DOUT)
                                 : (abn_keys + (size_t)(j - 512) * DOUT);
    const float* w2 = cls_mem_w + DOUT;
    float kv = 0.f, kn = 0.f;
#pragma unroll
    for (int t = 0; t < 4; t++) {
        const int c = (lane + t * 32) * 4;
        float4 k4 = *reinterpret_cast<const float4*>(key + c);
        float4 w4 = *reinterpret_cast<const float4*>(w2 + c);
        kv += k4.x * w4.x + k4.y * w4.y + k4.z * w4.z + k4.w * w4.w;
        kn += k4.x * k4.x + k4.y * k4.y + k4.z * k4.z + k4.w * k4.w;
        uint32_t hw0, lw0, hw1, lw1;
        split2_f16(k4.x, k4.y, hw0, lw0);
        split2_f16(k4.z, k4.w, hw1, lw1);
        const size_t e = (size_t)j * DOUT + c;
        *reinterpret_cast<uint2*>(g_Khi + e) = make_uint2(hw0, hw1);
        *reinterpret_cast<uint2*>(g_Klo + e) = make_uint2(lw0, lw1);
    }
#pragma unroll
    for (int o = 16; o; o >>= 1) {
        kv += __shfl_xor_sync(0xffffffffu, kv, o);
        kn += __shfl_xor_sync(0xffffffffu, kn, o);
    }
    if (lane == 0) { g_kv[j] = kv; g_kkn[j] = kn; }
}

// ============================================================
// 3-pass fp16 MMA over one 128x128x64 chunk, pass-grouped issue with
// independent accumulators per pass (no RAW chains within a pass).
// 8 warps as 4(M)x2(N): warp tile 32x64.
// ============================================================
__device__ __forceinline__ void mma_chunk_sw(uint32_t st,
                                             float accf[2][8][4],
                                             uint32_t acc1[2][8][2],
                                             uint32_t acc2[2][8][2],
                                             int wm, int wn, int lane)
{
    const int lrow  = lane & 15;
    const int khalf = lane >> 4;
#pragma unroll
    for (int ks = 0; ks < 4; ks++) {
        const uint32_t kb = ks * 32 + khalf * 16;
        uint32_t ah[2][4], al[2][4];
#pragma unroll
        for (int mf = 0; mf < 2; mf++) {
            const uint32_t ro = (uint32_t)((wm + mf * 16 + lrow) * 128) + kb;
            LDMATRIX_X4(ah[mf][0], ah[mf][1], ah[mf][2], ah[mf][3], st + M_AH + SW128(ro));
            LDMATRIX_X4(al[mf][0], al[mf][1], al[mf][2], al[mf][3], st + M_AL + SW128(ro));
        }
        uint32_t bh[4][4], bl[4][4];
#pragma unroll
        for (int nq = 0; nq < 4; nq++) {
            const uint32_t ro = (uint32_t)((wn + nq * 16 + lrow) * 128) + kb;
            LDMATRIX_X4(bh[nq][0], bh[nq][1], bh[nq][2], bh[nq][3], st + M_BH + SW128(ro));
            LDMATRIX_X4(bl[nq][0], bl[nq][1], bl[nq][2], bl[nq][3], st + M_BL + SW128(ro));
        }
        // pass 1: AhBh -> f32 (16 independent MMAs)
#pragma unroll
        for (int mf = 0; mf < 2; mf++)
#pragma unroll
            for (int nq = 0; nq < 4; nq++)
#pragma unroll
                for (int nh = 0; nh < 2; nh++)
                    MMA_F16_F32(accf[mf][nq * 2 + nh], ah[mf], bh[nq][nh], bh[nq][nh + 2]);
        // pass 2: AhBl -> f16 acc1 (16 independent MMAs)
#pragma unroll
        for (int mf = 0; mf < 2; mf++)
#pragma unroll
            for (int nq = 0; nq < 4; nq++)
#pragma unroll
                for (int nh = 0; nh < 2; nh++)
                    MMA_F16_F16(acc1[mf][nq * 2 + nh], ah[mf], bl[nq][nh], bl[nq][nh + 2]);
        // pass 3: AlBh -> f16 acc2 (16 independent MMAs)
#pragma unroll
        for (int mf = 0; mf < 2; mf++)
#pragma unroll
            for (int nq = 0; nq < 4; nq++)
#pragma unroll
                for (int nh = 0; nh < 2; nh++)
                    MMA_F16_F16(acc2[mf][nq * 2 + nh], al[mf], bh[nq][nh], bh[nq][nh + 2]);
    }
}

__device__ __forceinline__ float frag_val(const float accf[4], const uint32_t acc1[2],
                                          const uint32_t acc2[2], int idx) {
    const __half2 c1 = *reinterpret_cast<const __half2*>(&acc1[idx >> 1]);
    const __half2 c2 = *reinterpret_cast<const __half2*>(&acc2[idx >> 1]);
    const float k1 = (idx & 1) ? __high2float(c1) : __low2float(c1);
    const float k2 = (idx & 1) ? __high2float(c2) : __low2float(c2);
    return accf[idx] + (k1 + k2);
}

#define DECL_ACCS \
    float    accf[2][8][4]; \
    uint32_t acc1[2][8][2]; \
    uint32_t acc2[2][8][2]; \
    _Pragma("unroll") \
    for (int i = 0; i < 2; i++) \
        _Pragma("unroll") \
        for (int j = 0; j < 8; j++) { \
            _Pragma("unroll") \
            for (int c = 0; c < 4; c++) accf[i][j][c] = 0.f; \
            acc1[i][j][0] = 0u; acc1[i][j][1] = 0u; \
            acc2[i][j][0] = 0u; acc2[i][j][1] = 0u; \
        }

// ============================================================
// Winograd GEMM: M_p = U_p @ V_p^T  (6 points, 2048x512x2048 each)
// ============================================================
__global__ void __launch_bounds__(256, 1) wino_gemm_kernel(
    const __grid_constant__ CUtensorMap mUh,
    const __grid_constant__ CUtensorMap mUl,
    const __grid_constant__ CUtensorMap mVh,
    const __grid_constant__ CUtensorMap mVl)
{
    extern __shared__ char smem[];
    const uint32_t sb = smem_u32(smem);
    const int tid  = threadIdx.x;
    const int wid  = tid >> 5;
    const int lane = tid & 31;
    const int bm = blockIdx.y * 128;
    const int bn = blockIdx.x * 128;
    const int p  = blockIdx.z;
    const int wm = (wid >> 1) * 32;
    const int wn = (wid & 1) * 64;

    DECL_ACCS

    if (tid == 0) {
        MBARRIER_INIT(sb + 0, 1);
        MBARRIER_INIT(sb + 8, 1);
        MBARRIER_INIT(sb + 16, 1);
    }
    __syncthreads();

    const int CHUNKS = DIN / 64;   // 32
    auto issue = [&](int i) {
        const int s = i % NSTAGE;
        const uint32_t st = sb + STG_BASE + s * STG_BYTES;
        const uint32_t mb = sb + s * 8;
        const int k0 = i * 64;
        MBARRIER_EXPECT_TX(mb, STG_BYTES);
        TMA_2D(st + M_AH, &mUh, k0, p * GT + bm, mb);
        TMA_2D(st + M_AL, &mUl, k0, p * GT + bm, mb);
        TMA_2D(st + M_BH, &mVh, k0, p * DOUT + bn, mb);
        TMA_2D(st + M_BL, &mVl, k0, p * DOUT + bn, mb);
    };
    if (tid == 0) { issue(0); issue(1); issue(2); }

    for (int i = 0; i < CHUNKS; i++) {
        const int s = i % NSTAGE;
        MBARRIER_WAIT_PARITY(sb + s * 8, (uint32_t)((i / NSTAGE) & 1));
        mma_chunk_sw(sb + STG_BASE + s * STG_BYTES, accf, acc1, acc2, wm, wn, lane);
        __syncthreads();
        if (tid == 0 && i + NSTAGE < CHUNKS) issue(i + NSTAGE);
    }

#pragma unroll
    for (int mf = 0; mf < 2; mf++) {
        const int row0 = bm + wm + mf * 16 + (lane >> 2);
#pragma unroll
        for (int nf = 0; nf < 8; nf++) {
            const int col = bn + wn + nf * 8 + (lane & 3) * 2;
#pragma unroll
            for (int h = 0; h < 2; h++) {
                const int row = row0 + h * 8;
                *reinterpret_cast<float2*>(
                    g_M + ((size_t)(p * GT) + row) * DOUT + col) =
                    make_float2(frag_val(accf[mf][nf], acc1[mf][nf], acc2[mf][nf], 2 * h),
                                frag_val(accf[mf][nf], acc1[mf][nf], acc2[mf][nf], 2 * h + 1));
            }
        }
    }
}

// ============================================================
// Winograd output transform + bias + relu -> E, fused rowstats
// ============================================================
__global__ void __launch_bounds__(256) wino_out_kernel(
    const float* __restrict__ bias,
    const float* __restrict__ cls_w,
    const float* __restrict__ cls_b,
    const float* __restrict__ cls_mem_w,
    float* __restrict__ E,
    float* __restrict__ p_out)
{
    const int gt = blockIdx.x;
    const int o  = threadIdx.x * 2;
    float2 m[6];
#pragma unroll
    for (int p = 0; p < 6; p++)
        m[p] = *reinterpret_cast<const float2*>(g_M + ((size_t)(p * GT) + gt) * DOUT + o);

    float ya[4], yb[4];
    ya[0] = m[0].x + m[1].x + m[2].x + m[3].x + m[4].x;
    yb[0] = m[0].y + m[1].y + m[2].y + m[3].y + m[4].y;
    ya[1] = m[1].x - m[2].x + 2.f * (m[3].x - m[4].x);
    yb[1] = m[1].y - m[2].y + 2.f * (m[3].y - m[4].y);
    ya[2] = m[1].x + m[2].x + 4.f * (m[3].x + m[4].x);
    yb[2] = m[1].y + m[2].y + 4.f * (m[3].y + m[4].y);
    ya[3] = m[1].x - m[2].x + 8.f * (m[3].x - m[4].x) + m[5].x;
    yb[3] = m[1].y - m[2].y + 8.f * (m[3].y - m[4].y) + m[5].y;

    const float2 b  = *reinterpret_cast<const float2*>(bias + o);
    const float2 w0 = *reinterpret_cast<const float2*>(cls_w + o);
    const float2 w1 = *reinterpret_cast<const float2*>(cls_mem_w + o);

    __shared__ float red[8][12];
    const int lane = threadIdx.x & 31, wrp = threadIdx.x >> 5;

    float d0[4], d1[4], qq[4];
#pragma unroll
    for (int r = 0; r < 4; r++) {
        const float v0 = fmaxf(ya[r] + b.x, 0.f);
        const float v1 = fmaxf(yb[r] + b.y, 0.f);
        const int row = 4 * gt + r;
        *reinterpret_cast<float2*>(E + (size_t)row * DOUT + o) = make_float2(v0, v1);
        uint32_t hw, lw;
        split2_f16(v0, v1, hw, lw);
        *reinterpret_cast<uint32_t*>(g_Ehi + (size_t)row * DOUT + o) = hw;
        *reinterpret_cast<uint32_t*>(g_Elo + (size_t)row * DOUT + o) = lw;
        d0[r] = v0 * w0.x + v1 * w0.y;
        d1[r] = v0 * w1.x + v1 * w1.y;
        qq[r] = v0 * v0 + v1 * v1;
    }
#pragma unroll
    for (int r = 0; r < 4; r++) {
#pragma unroll
        for (int off = 16; off; off >>= 1) {
            d0[r] += __shfl_xor_sync(0xffffffffu, d0[r], off);
            d1[r] += __shfl_xor_sync(0xffffffffu, d1[r], off);
            qq[r] += __shfl_xor_sync(0xffffffffu, qq[r], off);
        }
        if (lane == 0) {
            red[wrp][3 * r + 0] = d0[r];
            red[wrp][3 * r + 1] = d1[r];
            red[wrp][3 * r + 2] = qq[r];
        }
    }
    __syncthreads();
    if (threadIdx.x < 12) {
        float s = 0.f;
#pragma unroll
        for (int w = 0; w < 8; w++) s += red[w][threadIdx.x];
        const int r = threadIdx.x / 3, q = threadIdx.x - 3 * r;
        const int row = 4 * gt + r;
        if (q == 0)      p_out[row]   = 1.f / (1.f + __expf(-(s + cls_b[0])));
        else if (q == 1) g_w1dot[row] = s;
        else             g_qq[row]    = s;
    }
}

// ============================================================
// score GEMM: S = E @ keys^T, tile 128x128, K=512, TMA feed
// ============================================================
__global__ void __launch_bounds__(256, 1) score_mma_kernel(
    const __grid_constant__ CUtensorMap mEh,
    const __grid_constant__ CUtensorMap mEl,
    const __grid_constant__ CUtensorMap mKh,
    const __grid_constant__ CUtensorMap mKl)
{
    extern __shared__ char smem[];
    const uint32_t sb = smem_u32(smem);
    const int tid  = threadIdx.x;
    const int wid  = tid >> 5;
    const int lane = tid & 31;
    const int bm = blockIdx.y * 128;
    const int bn = blockIdx.x * 128;
    const int wm = (wid >> 1) * 32;
    const int wn = (wid & 1) * 64;

    DECL_ACCS

    if (tid == 0) {
        MBARRIER_INIT(sb + 0, 1);
        MBARRIER_INIT(sb + 8, 1);
        MBARRIER_INIT(sb + 16, 1);
    }
    __syncthreads();

    const int CHUNKS = DOUT / 64;   // 8
    auto issue = [&](int i) {
        const int s = i % NSTAGE;
        const uint32_t st = sb + STG_BASE + s * STG_BYTES;
        const uint32_t mb = sb + s * 8;
        const int k0 = i * 64;
        MBARRIER_EXPECT_TX(mb, STG_BYTES);
        TMA_2D(st + M_AH, &mEh, k0, bm, mb);
        TMA_2D(st + M_AL, &mEl, k0, bm, mb);
        TMA_2D(st + M_BH, &mKh, k0, bn, mb);
        TMA_2D(st + M_BL, &mKl, k0, bn, mb);
    };
    if (tid == 0) { issue(0); issue(1); issue(2); }

    for (int i = 0; i < CHUNKS; i++) {
        const int s = i % NSTAGE;
        MBARRIER_WAIT_PARITY(sb + s * 8, (uint32_t)((i / NSTAGE) & 1));
        mma_chunk_sw(sb + STG_BASE + s * STG_BYTES, accf, acc1, acc2, wm, wn, lane);
        __syncthreads();
        if (tid == 0 && i + NSTAGE < CHUNKS) issue(i + NSTAGE);
    }

#pragma unroll
    for (int mf = 0; mf < 2; mf++) {
        const int row0 = bm + wm + mf * 16 + (lane >> 2);
#pragma unroll
        for (int nf = 0; nf < 8; nf++) {
            const int col = bn + wn + nf * 8 + (lane & 3) * 2;
#pragma unroll
            for (int h = 0; h < 2; h++) {
                const int row = row0 + h * 8;
                *reinterpret_cast<float2*>(g_S + (size_t)row * NKEYS + col) =
                    make_float2(frag_val(accf[mf][nf], acc1[mf][nf], acc2[mf][nf], 2 * h),
                                frag_val(accf[mf][nf], acc1[mf][nf], acc2[mf][nf], 2 * h + 1));
            }
        }
    }
}

// ============================================================
// softmax / argmax reduction over S rows
// ============================================================
__global__ void softmax_reduce_kernel(const float* __restrict__ cls_mem_b,
                                      float* __restrict__ up_out,
                                      float* __restrict__ nor_out,
                                      float* __restrict__ abn_out)
{
    const int row  = blockIdx.x * 8 + (threadIdx.x >> 5);
    const int lane = threadIdx.x & 31;
    const float* Sr = g_S + (size_t)row * NKEYS;

    float s[32];
    float m = -INFINITY;
    float bv0 = -INFINITY, bv1 = -INFINITY;
    int bi0 = 0, bi1 = 0;
#pragma unroll
    for (int t = 0; t < 32; t++) {
        const int j = t * 32 + lane;
        const float v = Sr[j];
        s[t] = v;
        m = fmaxf(m, v);
        if (t < 16) { if (v > bv0) { bv0 = v; bi0 = j; } }
        else        { if (v > bv1) { bv1 = v; bi1 = j; } }
    }
#pragma unroll
    for (int o = 16; o; o >>= 1) m = fmaxf(m, __shfl_xor_sync(0xffffffffu, m, o));

    float l = 0.f, dsum = 0.f;
#pragma unroll
    for (int t = 0; t < 32; t++) {
        const int j = t * 32 + lane;
        const float e = __expf(s[t] - m);
        l += e;
        dsum += e * g_kv[j];
    }
#pragma unroll
    for (int o = 16; o; o >>= 1) {
        l    += __shfl_xor_sync(0xffffffffu, l, o);
        dsum += __shfl_xor_sync(0xffffffffu, dsum, o);
    }
#pragma unroll
    for (int o = 16; o; o >>= 1) {
        const float o0 = __shfl_xor_sync(0xffffffffu, bv0, o);
        const int   i0 = __shfl_xor_sync(0xffffffffu, bi0, o);
        if (o0 > bv0 || (o0 == bv0 && i0 < bi0)) { bv0 = o0; bi0 = i0; }
        const float o1 = __shfl_xor_sync(0xffffffffu, bv1, o);
        const int   i1 = __shfl_xor_sync(0xffffffffu, bi1, o);
        if (o1 > bv1 || (o1 == bv1 && i1 < bi1)) { bv1 = o1; bi1 = i1; }
    }
    if (lane == 0) {
        const float x = g_w1dot[row] + dsum / l + cls_mem_b[0];
        up_out[row] = 1.f / (1.f + __expf(-x));
        const float qq = g_qq[row];
        nor_out[row] = (qq - 2.f * bv0 + g_kkn[bi0]) * (1.f / 512.f);
        abn_out[row] = (qq - 2.f * bv1 + g_kkn[bi1]) * (1.f / 512.f);
    }
}

// ============================================================
// host: tensormap construction (driver entry point via cudart; no -lcuda)
// ============================================================
typedef CUresult (*PFN_tmEnc)(CUtensorMap*, CUtensorMapDataType, cuuint32_t, void*,
                              const cuuint64_t*, const cuuint64_t*, const cuuint32_t*,
                              const cuuint32_t*, CUtensorMapInterleave, CUtensorMapSwizzle,
                              CUtensorMapL2promotion, CUtensorMapFloatOOBfill);

static void enc2d(PFN_tmEnc f, CUtensorMap* m, void* addr,
                  unsigned long long d0, unsigned long long d1,
                  unsigned long long stride_bytes)
{
    cuuint64_t dims[2]    = {(cuuint64_t)d0, (cuuint64_t)d1};
    cuuint64_t strides[1] = {(cuuint64_t)stride_bytes};
    cuuint32_t box[2]     = {64u, 128u};
    cuuint32_t es[2]      = {1u, 1u};
    f(m, CU_TENSOR_MAP_DATA_TYPE_FLOAT16, 2, addr, dims, strides, box, es,
      CU_TENSOR_MAP_INTERLEAVE_NONE, CU_TENSOR_MAP_SWIZZLE_128B,
      CU_TENSOR_MAP_L2_PROMOTION_L2_128B, CU_TENSOR_MAP_FLOAT_OOB_FILL_NONE);
}

extern "C" void kernel_launch(void* const* d_in, const int* in_sizes, int n_in,
                              void* d_out, int out_size)
{
    const float* ref_nor   = (const float*)d_in[0];
    // d_in[1] = ref_abn : dead (only feeds the discarded p_score[B:])
    const float* nor_keys  = (const float*)d_in[2];
    const float* abn_keys  = (const float*)d_in[3];
    const float* conv_w    = (const float*)d_in[4];
    const float* conv_b    = (const float*)d_in[5];
    const float* cls_w     = (const float*)d_in[6];
    const float* cls_b     = (const float*)d_in[7];
    const float* cls_mem_w = (const float*)d_in[8];
    const float* cls_mem_b = (const float*)d_in[9];

    float* out      = (float*)d_out;
    float* p_score  = out;
    float* up_score = out + ROWS;
    float* nor_loss = out + 2 * ROWS;
    float* abn_loss = out + 3 * ROWS;
    float* E        = out + 4 * ROWS;

    PFN_tmEnc enc = nullptr;
    cudaDriverEntryPointQueryResult qr;
    cudaGetDriverEntryPoint("cuTensorMapEncodeTiled", (void**)&enc,
                            cudaEnableDefault, &qr);
    void *pUh, *pUl, *pVh, *pVl, *pEh, *pEl, *pKh, *pKl;
    cudaGetSymbolAddress(&pUh, g_Uhi); cudaGetSymbolAddress(&pUl, g_Ulo);
    cudaGetSymbolAddress(&pVh, g_Vhi); cudaGetSymbolAddress(&pVl, g_Vlo);
    cudaGetSymbolAddress(&pEh, g_Ehi); cudaGetSymbolAddress(&pEl, g_Elo);
    cudaGetSymbolAddress(&pKh, g_Khi); cudaGetSymbolAddress(&pKl, g_Klo);

    CUtensorMap mUh, mUl, mVh, mVl, mEh, mEl, mKh, mKl;
    enc2d(enc, &mUh, pUh, DIN,  NPTS * GT,   (unsigned long long)DIN  * 2);
    enc2d(enc, &mUl, pUl, DIN,  NPTS * GT,   (unsigned long long)DIN  * 2);
    enc2d(enc, &mVh, pVh, DIN,  NPTS * DOUT, (unsigned long long)DIN  * 2);
    enc2d(enc, &mVl, pVl, DIN,  NPTS * DOUT, (unsigned long long)DIN  * 2);
    enc2d(enc, &mEh, pEh, DOUT, ROWS,        (unsigned long long)DOUT * 2);
    enc2d(enc, &mEl, pEl, DOUT, ROWS,        (unsigned long long)DOUT * 2);
    enc2d(enc, &mKh, pKh, DOUT, NKEYS,       (unsigned long long)DOUT * 2);
    enc2d(enc, &mKl, pKl, DOUT, NKEYS,       (unsigned long long)DOUT * 2);

    cudaFuncSetAttribute(wino_gemm_kernel,  cudaFuncAttributeMaxDynamicSharedMemorySize, SMEM_BYTES);
    cudaFuncSetAttribute(score_mma_kernel, cudaFuncAttributeMaxDynamicSharedMemorySize, SMEM_BYTES);

    wino_weight_kernel<<<(DOUT * DIN / 2) / 256, 256>>>(conv_w);
    wino_input_kernel<<<GT, 256>>>(ref_nor);
    keys_kernel<<<128, 256>>>(nor_keys, abn_keys, cls_mem_w);

    wino_gemm_kernel<<<dim3(4, 16, 6), 256, SMEM_BYTES>>>(mUh, mUl, mVh, mVl);
    wino_out_kernel<<<GT, 256>>>(conv_b, cls_w, cls_b, cls_mem_w, E, p_score);
    score_mma_kernel<<<dim3(8, 64), 256, SMEM_BYTES>>>(mEh, mEl, mKh, mKl);
    softmax_reduce_kernel<<<1024, 256>>>(cls_mem_b, up_score, nor_loss, abn_loss);
}